// round 12
// baseline (speedup 1.0000x reference)
#include <cuda_runtime.h>
#include <cuda_bf16.h>
#include <cuda_fp16.h>
#include <cstdint>

#define EMBED   1024
#define NHEADS  16
#define DK      64
#define BATCH   8
#define SEQ     4096
#define MTOK    (BATCH * SEQ)      /* 32768 tokens */
#define BHEADS  (BATCH * NHEADS)   /* 128 head-instances */
#define NCHUNK  8
#define SCHUNK  (SEQ / NCHUNK)     /* 512 */

// ---------------------------------------------------------------------------
// Scratch (__device__ globals: the sanctioned no-alloc workaround)
// ---------------------------------------------------------------------------
__device__ float g_QKV[3][MTOK * EMBED];                     // fp32 Q,K,V
__device__ float g_Gpart[NCHUNK * BHEADS * DK * DK];         // gram partials
__device__ float g_At[BHEADS * DK * DK];                     // attn transposed [e][d]
__device__ __half g_xh[MTOK * EMBED];                        // x fp16 hi
__device__ __half g_xl[MTOK * EMBED];                        // x fp16 lo (residual)
__device__ __half g_w[3][EMBED * EMBED];                     // W fp16 (q,k,v)

// ---------------------------------------------------------------------------
// helpers
// ---------------------------------------------------------------------------
static __device__ __forceinline__ uint32_t smem_u32(const void* p) {
    uint32_t a;
    asm("{ .reg .u64 t; cvta.to.shared.u64 t, %1; cvt.u32.u64 %0, t; }"
        : "=r"(a) : "l"(p));
    return a;
}
static __device__ __forceinline__ void cp16(uint32_t dst, const void* src) {
    asm volatile("cp.async.cg.shared.global [%0], [%1], 16;" :: "r"(dst), "l"(src));
}
#define CP_COMMIT()  asm volatile("cp.async.commit_group;" ::: "memory")
#define CP_WAIT(n)   asm volatile("cp.async.wait_group %0;" :: "n"(n) : "memory")

// mma.sync m16n8k16 row.col f32.f16.f16.f32 (baseline sm_80+ path)
static __device__ __forceinline__ void hmma(float* c, const uint32_t* a,
                                            uint32_t b0, uint32_t b1) {
    asm volatile(
        "mma.sync.aligned.m16n8k16.row.col.f32.f16.f16.f32 "
        "{%0,%1,%2,%3}, {%4,%5,%6,%7}, {%8,%9}, {%0,%1,%2,%3};"
        : "+f"(c[0]), "+f"(c[1]), "+f"(c[2]), "+f"(c[3])
        : "r"(a[0]), "r"(a[1]), "r"(a[2]), "r"(a[3]), "r"(b0), "r"(b1));
}
// ldmatrix x4: fills 4 fragment regs from 4 8x8 b16 tiles (lane-group addressed)
static __device__ __forceinline__ void ldsm4(uint32_t* r, uint32_t addr) {
    asm volatile("ldmatrix.sync.aligned.m8n8.x4.shared.b16 {%0,%1,%2,%3}, [%4];"
                 : "=r"(r[0]), "=r"(r[1]), "=r"(r[2]), "=r"(r[3]) : "r"(addr));
}

// packed fp32x2 helpers (for the fp32 attention kernels)
__device__ __forceinline__ void ffma2(unsigned long long &d, unsigned long long a,
                                      unsigned long long b) {
    asm("fma.rn.f32x2 %0, %1, %2, %0;" : "+l"(d) : "l"(a), "l"(b));
}
__device__ __forceinline__ unsigned long long dup2(float x) {
    unsigned long long r; unsigned xi = __float_as_uint(x);
    asm("mov.b64 %0, {%1, %1};" : "=l"(r) : "r"(xi));
    return r;
}
__device__ __forceinline__ float lo2(unsigned long long v) {
    return __uint_as_float((unsigned)(v & 0xffffffffull));
}
__device__ __forceinline__ float hi2(unsigned long long v) {
    return __uint_as_float((unsigned)(v >> 32));
}

// ---------------------------------------------------------------------------
// GEMM configuration
// ---------------------------------------------------------------------------
#define GBK        32
#define G_NCH      (EMBED / GBK)        /* 32 chunks */
#define PADW       40                   /* fp16 per padded row */
#define ROWB       (PADW * 2)           /* 80 bytes per row */
#define MAT_BYTES  (128 * ROWB)         /* 10240 */
#define STAGE_B    (3 * MAT_BYTES)      /* 30720 */
#define G_SMEM     (2 * STAGE_B)        /* 61440 */
#define GEMM_BLOCKS (EMBED / 128 * (MTOK / 128))   /* 8 * 256 = 2048 */
#define GRAM_BLOCKS (BHEADS * NCHUNK)              /* 1024 */

// 512 threads: each thread issues exactly one cp16 per matrix
static __device__ __forceinline__ void load_chunk(
    uint32_t sb, int buf, int c, int m0, int n0,
    const __half* __restrict__ Ah, const __half* __restrict__ Al,
    const __half* __restrict__ B, int tid)
{
    const uint32_t st = sb + buf * STAGE_B;
    const int row = tid >> 2;                // 0..127
    const int seg = tid & 3;                 // 16B segment (8 fp16)
    const uint32_t d = row * ROWB + seg * 16;
    const size_t gA = (size_t)(m0 + row) * EMBED + c * GBK + seg * 8;
    const size_t gB = (size_t)(n0 + row) * EMBED + c * GBK + seg * 8;
    cp16(st + 0 * MAT_BYTES + d, Ah + gA);
    cp16(st + 1 * MAT_BYTES + d, Al + gA);
    cp16(st + 2 * MAT_BYTES + d, B + gB);
    CP_COMMIT();
}

// GEMM body: C = (Xh + Xl) * W^T + bias  (2 HMMA passes, fp32 accumulators)
// 512 threads, 16 warps in 4(M) x 4(N), warp tile 32x32.
static __device__ __forceinline__ void gemm_body(
    char* smem, int bx,
    const __half* __restrict__ Ah, const __half* __restrict__ Al,
    const __half* __restrict__ B, const float* __restrict__ bias,
    float* __restrict__ C)
{
    const uint32_t sb = smem_u32(smem);
    const int tid  = threadIdx.x;
    const int wid  = tid >> 5;           // 0..15
    const int lane = tid & 31;
    const int g    = lane >> 2;          // c-fragment row group 0..7
    const int tg   = lane & 3;           // c-fragment col pair 0..3

    const int n0 = (bx & 7) * 128;       // n fastest: CTAs sharing m0 reuse A in L2
    const int m0 = (bx >> 3) * 128;

    const int wm = wid & 3;              // 0..3 -> M offset (32 rows each)
    const int wn = wid >> 2;             // 0..3 -> N offset (32 cols each)

    const int grp = lane >> 3, lr8 = lane & 7;
    const uint32_t aoff = (uint32_t)((wm * 32 + (grp & 1) * 8 + lr8) * ROWB
                                     + (grp >> 1) * 16);
    const uint32_t boff = (uint32_t)((wn * 32 + (grp >> 1) * 8 + lr8) * ROWB
                                     + (grp & 1) * 16);

    float acc[2][4][4];
    #pragma unroll
    for (int mt = 0; mt < 2; mt++)
        #pragma unroll
        for (int nt = 0; nt < 4; nt++)
            #pragma unroll
            for (int r = 0; r < 4; r++) acc[mt][nt][r] = 0.f;

    load_chunk(sb, 0, 0, m0, n0, Ah, Al, B, tid);

    for (int c = 0; c < G_NCH; c++) {
        const int buf = c & 1;
        if (c + 1 < G_NCH) {
            load_chunk(sb, buf ^ 1, c + 1, m0, n0, Ah, Al, B, tid);
            CP_WAIT(1);
        } else {
            CP_WAIT(0);
        }
        __syncthreads();

        const uint32_t stAh = sb + buf * STAGE_B;
        const uint32_t stAl = stAh + MAT_BYTES;
        const uint32_t stB  = stAh + 2 * MAT_BYTES;

        #pragma unroll
        for (int step = 0; step < 2; step++) {
            const uint32_t so = step * 32;       // 16 fp16 = 32 B along k

            uint32_t ah[2][4], al[2][4];
            #pragma unroll
            for (int mt = 0; mt < 2; mt++) {
                ldsm4(ah[mt], stAh + aoff + mt * (16 * ROWB) + so);
                ldsm4(al[mt], stAl + aoff + mt * (16 * ROWB) + so);
            }
            // B fragments loaded ONCE, reused by both split passes
            uint32_t b0[4], b1[4];
            ldsm4(b0, stB + boff + so);                   // n cols 0..15
            ldsm4(b1, stB + boff + 16 * ROWB + so);       // n cols 16..31

            // pass 0: xh * W  (8 HMMA, all-distinct accumulators)
            hmma(acc[0][0], ah[0], b0[0], b0[1]);
            hmma(acc[0][1], ah[0], b0[2], b0[3]);
            hmma(acc[1][0], ah[1], b0[0], b0[1]);
            hmma(acc[1][1], ah[1], b0[2], b0[3]);
            hmma(acc[0][2], ah[0], b1[0], b1[1]);
            hmma(acc[0][3], ah[0], b1[2], b1[3]);
            hmma(acc[1][2], ah[1], b1[0], b1[1]);
            hmma(acc[1][3], ah[1], b1[2], b1[3]);
            // pass 1: xl * W  (RAW distance 8)
            hmma(acc[0][0], al[0], b0[0], b0[1]);
            hmma(acc[0][1], al[0], b0[2], b0[3]);
            hmma(acc[1][0], al[1], b0[0], b0[1]);
            hmma(acc[1][1], al[1], b0[2], b0[3]);
            hmma(acc[0][2], al[0], b1[0], b1[1]);
            hmma(acc[0][3], al[0], b1[2], b1[3]);
            hmma(acc[1][2], al[1], b1[0], b1[1]);
            hmma(acc[1][3], al[1], b1[2], b1[3]);
        }
        __syncthreads();
    }

    #pragma unroll
    for (int mt = 0; mt < 2; mt++) {
        const int row = m0 + wm * 32 + mt * 16 + g;
        #pragma unroll
        for (int nt = 0; nt < 4; nt++) {
            const int col = n0 + wn * 32 + nt * 8 + 2 * tg;
            const float2 bv = *(const float2*)&bias[col];
            float2 v0 = make_float2(acc[mt][nt][0] + bv.x, acc[mt][nt][1] + bv.y);
            float2 v1 = make_float2(acc[mt][nt][2] + bv.x, acc[mt][nt][3] + bv.y);
            *(float2*)&C[(size_t)row * EMBED + col]       = v0;
            *(float2*)&C[(size_t)(row + 8) * EMBED + col] = v1;
        }
    }
}

// Gram body (512 threads): Gpart[c][bh][d][e] = sum_{s in chunk} Q.K
// Each thread: rows {ty, ty+32} x 4 cols, via f32x2.
static __device__ __forceinline__ void gram_body(char* smem, int bh, int chunk)
{
    float (*Qs)[64] = (float(*)[64])smem;
    float (*Ks)[64] = (float(*)[64])(smem + 64 * 64 * 4);

    const int b = bh >> 4, h = bh & 15;
    const float* Q = g_QKV[0];
    const float* K = g_QKV[1];
    const size_t base = ((size_t)b * SEQ + (size_t)chunk * SCHUNK) * EMBED + h * DK;

    const int tid = threadIdx.x;
    const int tx = tid & 15;             // 0..15 -> e col group (4 cols)
    const int ty = tid >> 4;             // 0..31 -> d rows ty, ty+32
    const int lr = tid >> 4;             // 0..31 (load rows, stepped by 32)
    const int lc4 = (tid & 15) << 2;

    unsigned long long c2[2][2];
    c2[0][0] = c2[0][1] = c2[1][0] = c2[1][1] = 0ull;

    for (int st = 0; st < SCHUNK / 64; st++) {
        #pragma unroll
        for (int rr = 0; rr < 64; rr += 32) {
            const int s = rr + lr;
            const size_t gg = base + (size_t)(st * 64 + s) * EMBED + lc4;
            *(float4*)&Qs[s][lc4] = *(const float4*)(Q + gg);
            *(float4*)&Ks[s][lc4] = *(const float4*)(K + gg);
        }
        __syncthreads();

        #pragma unroll 8
        for (int ss = 0; ss < 64; ss++) {
            const float qa = Qs[ss][ty];
            const float qb = Qs[ss][ty + 32];
            ulonglong2 k2 = *(const ulonglong2*)&Ks[ss][tx * 4];
            unsigned long long da = dup2(qa), db = dup2(qb);
            ffma2(c2[0][0], da, k2.x);
            ffma2(c2[0][1], da, k2.y);
            ffma2(c2[1][0], db, k2.x);
            ffma2(c2[1][1], db, k2.y);
        }
        __syncthreads();
    }

    float* gp = g_Gpart + ((size_t)chunk * BHEADS + bh) * DK * DK;
    *(float4*)&gp[ty * DK + tx * 4] =
        make_float4(lo2(c2[0][0]), hi2(c2[0][0]), lo2(c2[0][1]), hi2(c2[0][1]));
    *(float4*)&gp[(ty + 32) * DK + tx * 4] =
        make_float4(lo2(c2[1][0]), hi2(c2[1][0]), lo2(c2[1][1]), hi2(c2[1][1]));
}

// ---------------------------------------------------------------------------
// Kernel A: fused prep — x hi/lo split + 3x W fp16 convert, one launch.
// ---------------------------------------------------------------------------
#define XB  ((MTOK * EMBED) / 1024)     /* 32768 blocks */
#define WB  ((EMBED * EMBED) / 1024)    /* 1024 blocks per W */

__global__ __launch_bounds__(256)
void prep_kernel(const float* __restrict__ x,
                 const float* __restrict__ Wq, const float* __restrict__ Wk,
                 const float* __restrict__ Wv,
                 __half* __restrict__ xh, __half* __restrict__ xl,
                 __half* __restrict__ w0, __half* __restrict__ w1,
                 __half* __restrict__ w2)
{
    const int bx = blockIdx.x;
    if (bx < XB) {
        const int i = (bx * 256 + threadIdx.x) * 4;
        float4 v = *(const float4*)(x + i);
        __half h0 = __float2half_rn(v.x), h1 = __float2half_rn(v.y);
        __half h2 = __float2half_rn(v.z), h3 = __float2half_rn(v.w);
        __half l0 = __float2half_rn(v.x - __half2float(h0));
        __half l1 = __float2half_rn(v.y - __half2float(h1));
        __half l2 = __float2half_rn(v.z - __half2float(h2));
        __half l3 = __float2half_rn(v.w - __half2float(h3));
        __half2 hp0 = {h0, h1}, hp1 = {h2, h3};
        __half2 lp0 = {l0, l1}, lp1 = {l2, l3};
        *(__half2*)(xh + i)     = hp0;
        *(__half2*)(xh + i + 2) = hp1;
        *(__half2*)(xl + i)     = lp0;
        *(__half2*)(xl + i + 2) = lp1;
    } else {
        const int wi = (bx - XB) / WB;             // 0..2
        const int wb = (bx - XB) - wi * WB;
        const float* src = (wi == 0) ? Wq : (wi == 1) ? Wk : Wv;
        __half* dst = (wi == 0) ? w0 : (wi == 1) ? w1 : w2;
        const int i = (wb * 256 + threadIdx.x) * 4;
        float4 v = *(const float4*)(src + i);
        __half2 p0 = {__float2half_rn(v.x), __float2half_rn(v.y)};
        __half2 p1 = {__float2half_rn(v.z), __float2half_rn(v.w)};
        *(__half2*)(dst + i)     = p0;
        *(__half2*)(dst + i + 2) = p1;
    }
}

// ---------------------------------------------------------------------------
// Kernel B: standalone projection GEMM (used for Q and K)
// ---------------------------------------------------------------------------
__global__ __launch_bounds__(512, 2)
void gemm_split_kernel(const __half* __restrict__ Ah,
                       const __half* __restrict__ Al,
                       const __half* __restrict__ B,
                       const float* __restrict__ bias,
                       float* __restrict__ C)
{
    extern __shared__ char smem[];
    gemm_body(smem, blockIdx.x, Ah, Al, B, bias, C);
}

// ---------------------------------------------------------------------------
// Kernel C: FUSED V-projection GEMM + gram, interleaved 2:1.
// ---------------------------------------------------------------------------
__global__ __launch_bounds__(512, 2)
void vgemm_gram_kernel(const __half* __restrict__ Ah,
                       const __half* __restrict__ Al,
                       const __half* __restrict__ B,
                       const float* __restrict__ bias,
                       float* __restrict__ C)
{
    extern __shared__ char smem[];
    const int bx = blockIdx.x;
    const int r = bx % 3;
    if (r < 2) {
        const int gemm_id = (bx / 3) * 2 + r;        // 0..2047
        gemm_body(smem, gemm_id, Ah, Al, B, bias, C);
    } else {
        const int gram_id = bx / 3;                  // 0..1023
        gram_body(smem, gram_id & (BHEADS - 1), gram_id >> 7);
    }
}

// ---------------------------------------------------------------------------
// Kernel D: reduce partials + softmax; write attn transposed At[e][d]
// ---------------------------------------------------------------------------
__global__ __launch_bounds__(256)
void softmax_kernel()
{
    const int gwarp = (blockIdx.x * blockDim.x + threadIdx.x) >> 5;
    const int lane = threadIdx.x & 31;
    const int bh = gwarp >> 6;
    const int d = gwarp & 63;

    float g0 = 0.f, g1 = 0.f;
    #pragma unroll
    for (int c = 0; c < NCHUNK; c++) {
        const float* gp = g_Gpart + (((size_t)c * BHEADS + bh) * DK + d) * DK;
        g0 += gp[lane];
        g1 += gp[lane + 32];
    }
    g0 *= 0.125f; g1 *= 0.125f;

    float m = fmaxf(g0, g1);
    #pragma unroll
    for (int o = 16; o > 0; o >>= 1) m = fmaxf(m, __shfl_xor_sync(0xffffffffu, m, o));
    float e0 = expf(g0 - m), e1 = expf(g1 - m);
    float s = e0 + e1;
    #pragma unroll
    for (int o = 16; o > 0; o >>= 1) s += __shfl_xor_sync(0xffffffffu, s, o);
    const float inv = 1.0f / s;

    float* at = g_At + (size_t)bh * DK * DK;
    at[lane * DK + d]        = e0 * inv;
    at[(lane + 32) * DK + d] = e1 * inv;
}

// ---------------------------------------------------------------------------
// Kernel E: output mix  out[m, h*64+d] = sum_e attn[bh][d][e] * V[m, h*64+e]
// ---------------------------------------------------------------------------
__global__ __launch_bounds__(256, 2)
void out_kernel(float* __restrict__ OUT)
{
    __shared__ float Am[64][64];
    __shared__ float Vt[64][65];

    const int m0 = blockIdx.x * 64;
    const int h  = blockIdx.y;
    const int b  = m0 >> 12;
    const int bh = b * NHEADS + h;
    const float* V = g_QKV[2];

    const int tid = threadIdx.x;
    const int tx = tid & 15, ty = tid >> 4;
    const int lr = tid >> 4, lc4 = (tid & 15) << 2;

    const float* at = g_At + (size_t)bh * DK * DK;
    #pragma unroll
    for (int rr = 0; rr < 64; rr += 16)
        *(float4*)&Am[rr + lr][lc4] = *(const float4*)&at[(rr + lr) * DK + lc4];

    #pragma unroll
    for (int rr = 0; rr < 64; rr += 16) {
        const int s = rr + lr;
        float4 v = *(const float4*)(V + (size_t)(m0 + s) * EMBED + h * DK + lc4);
        Vt[lc4 + 0][s] = v.x;
        Vt[lc4 + 1][s] = v.y;
        Vt[lc4 + 2][s] = v.z;
        Vt[lc4 + 3][s] = v.w;
    }
    __syncthreads();

    unsigned long long o2[4][2];
    #pragma unroll
    for (int i = 0; i < 4; i++) { o2[i][0] = 0ull; o2[i][1] = 0ull; }

    #pragma unroll 8
    for (int ee = 0; ee < 64; ee++) {
        ulonglong2 ap = *(const ulonglong2*)&Am[ee][tx * 4];
        #pragma unroll
        for (int si = 0; si < 4; si++) {
            unsigned long long vd = dup2(Vt[ee][ty * 4 + si]);
            ffma2(o2[si][0], vd, ap.x);
            ffma2(o2[si][1], vd, ap.y);
        }
    }

    #pragma unroll
    for (int si = 0; si < 4; si++) {
        const int m = m0 + ty * 4 + si;
        *(float4*)&OUT[(size_t)m * EMBED + h * DK + tx * 4] =
            make_float4(lo2(o2[si][0]), hi2(o2[si][0]),
                        lo2(o2[si][1]), hi2(o2[si][1]));
    }
}

// ---------------------------------------------------------------------------
// Launch
// ---------------------------------------------------------------------------
extern "C" void kernel_launch(void* const* d_in, const int* in_sizes, int n_in,
                              void* d_out, int out_size)
{
    const float* x  = (const float*)d_in[0];
    const float* Wq = (const float*)d_in[1];
    const float* bq = (const float*)d_in[2];
    const float* Wk = (const float*)d_in[3];
    const float* bk = (const float*)d_in[4];
    const float* Wv = (const float*)d_in[5];
    const float* bv = (const float*)d_in[6];
    float* out = (float*)d_out;

    cudaFuncSetAttribute(gemm_split_kernel,
                         cudaFuncAttributeMaxDynamicSharedMemorySize, G_SMEM);
    cudaFuncSetAttribute(vgemm_gram_kernel,
                         cudaFuncAttributeMaxDynamicSharedMemorySize, G_SMEM);

    __half *xh, *xl, *wb;
    cudaGetSymbolAddress((void**)&xh, g_xh);
    cudaGetSymbolAddress((void**)&xl, g_xl);
    cudaGetSymbolAddress((void**)&wb, g_w);
    float* qkv;
    cudaGetSymbolAddress((void**)&qkv, g_QKV);

    __half* w0 = wb;
    __half* w1 = wb + EMBED * EMBED;
    __half* w2 = wb + 2 * EMBED * EMBED;

    // 1) fused conversions
    prep_kernel<<<XB + 3 * WB, 256>>>(x, Wq, Wk, Wv, xh, xl, w0, w1, w2);

    // 2) Q and K projections
    gemm_split_kernel<<<GEMM_BLOCKS, 512, G_SMEM>>>(xh, xl, w0, bq,
                                                    qkv + 0ll * MTOK * EMBED);
    gemm_split_kernel<<<GEMM_BLOCKS, 512, G_SMEM>>>(xh, xl, w1, bk,
                                                    qkv + 1ll * MTOK * EMBED);

    // 3) fused: V projection (tensor pipe) + gram over Q,K (fma pipe)
    vgemm_gram_kernel<<<GEMM_BLOCKS + GRAM_BLOCKS, 512, G_SMEM>>>(
        xh, xl, w2, bv, qkv + 2ll * MTOK * EMBED);

    // 4) softmax + output mix
    softmax_kernel<<<(BHEADS * DK) / 8, 256>>>();
    out_kernel<<<dim3(MTOK / 64, NHEADS), 256>>>(out);
}

// round 13
// speedup vs baseline: 1.2170x; 1.2170x over previous
#include <cuda_runtime.h>
#include <cuda_bf16.h>
#include <cuda_fp16.h>
#include <cstdint>

#define EMBED   1024
#define NHEADS  16
#define DK      64
#define BATCH   8
#define SEQ     4096
#define MTOK    (BATCH * SEQ)      /* 32768 tokens */
#define BHEADS  (BATCH * NHEADS)   /* 128 head-instances */
#define NCHUNK  8
#define SCHUNK  (SEQ / NCHUNK)     /* 512 */

// ---------------------------------------------------------------------------
// Scratch (__device__ globals: the sanctioned no-alloc workaround)
// ---------------------------------------------------------------------------
__device__ float g_QKV[3][MTOK * EMBED];                     // fp32 Q,K,V
__device__ float g_Gpart[NCHUNK * BHEADS * DK * DK];         // gram partials
__device__ float g_At[BHEADS * DK * DK];                     // attn transposed [e][d]
__device__ __half g_xh[MTOK * EMBED];                        // x fp16 hi
__device__ __half g_xl[MTOK * EMBED];                        // x fp16 lo (residual)
__device__ __half g_w[3][EMBED * EMBED];                     // W fp16 (q,k,v)

// ---------------------------------------------------------------------------
// helpers
// ---------------------------------------------------------------------------
static __device__ __forceinline__ uint32_t smem_u32(const void* p) {
    uint32_t a;
    asm("{ .reg .u64 t; cvta.to.shared.u64 t, %1; cvt.u32.u64 %0, t; }"
        : "=r"(a) : "l"(p));
    return a;
}
static __device__ __forceinline__ void cp16(uint32_t dst, const void* src) {
    asm volatile("cp.async.cg.shared.global [%0], [%1], 16;" :: "r"(dst), "l"(src));
}
#define CP_COMMIT()  asm volatile("cp.async.commit_group;" ::: "memory")
#define CP_WAIT(n)   asm volatile("cp.async.wait_group %0;" :: "n"(n) : "memory")

// mma.sync m16n8k16 row.col f32.f16.f16.f32 (baseline sm_80+ path)
static __device__ __forceinline__ void hmma(float* c, const uint32_t* a,
                                            uint32_t b0, uint32_t b1) {
    asm volatile(
        "mma.sync.aligned.m16n8k16.row.col.f32.f16.f16.f32 "
        "{%0,%1,%2,%3}, {%4,%5,%6,%7}, {%8,%9}, {%0,%1,%2,%3};"
        : "+f"(c[0]), "+f"(c[1]), "+f"(c[2]), "+f"(c[3])
        : "r"(a[0]), "r"(a[1]), "r"(a[2]), "r"(a[3]), "r"(b0), "r"(b1));
}
// ldmatrix x4: fills 4 fragment regs from 4 8x8 b16 tiles (lane-group addressed)
static __device__ __forceinline__ void ldsm4(uint32_t* r, uint32_t addr) {
    asm volatile("ldmatrix.sync.aligned.m8n8.x4.shared.b16 {%0,%1,%2,%3}, [%4];"
                 : "=r"(r[0]), "=r"(r[1]), "=r"(r[2]), "=r"(r[3]) : "r"(addr));
}

// packed fp32x2 helpers (for the fp32 attention kernels)
__device__ __forceinline__ void ffma2(unsigned long long &d, unsigned long long a,
                                      unsigned long long b) {
    asm("fma.rn.f32x2 %0, %1, %2, %0;" : "+l"(d) : "l"(a), "l"(b));
}
__device__ __forceinline__ unsigned long long dup2(float x) {
    unsigned long long r; unsigned xi = __float_as_uint(x);
    asm("mov.b64 %0, {%1, %1};" : "=l"(r) : "r"(xi));
    return r;
}
__device__ __forceinline__ float lo2(unsigned long long v) {
    return __uint_as_float((unsigned)(v & 0xffffffffull));
}
__device__ __forceinline__ float hi2(unsigned long long v) {
    return __uint_as_float((unsigned)(v >> 32));
}

// ---------------------------------------------------------------------------
// GEMM configuration (R11 shape: 256 threads, 8 warps 4Mx2N, warp tile 32x64)
// ---------------------------------------------------------------------------
#define GBK        32
#define G_NCH      (EMBED / GBK)        /* 32 chunks */
#define PADW       40                   /* fp16 per padded row */
#define ROWB       (PADW * 2)           /* 80 bytes per row */
#define MAT_BYTES  (128 * ROWB)         /* 10240 */
#define STAGE_B    (3 * MAT_BYTES)      /* 30720 */
#define G_SMEM     (2 * STAGE_B)        /* 61440 */
#define GEMM_BLOCKS (EMBED / 128 * (MTOK / 128))   /* 8 * 256 = 2048 */
#define GRAM_BLOCKS (BHEADS * NCHUNK)              /* 1024 */

template <bool TWO_PASS>
static __device__ __forceinline__ void load_chunk(
    uint32_t sb, int buf, int c, int m0, int n0,
    const __half* __restrict__ Ah, const __half* __restrict__ Al,
    const __half* __restrict__ B, int tid)
{
    const uint32_t st = sb + buf * STAGE_B;
    #pragma unroll
    for (int i = 0; i < 2; i++) {
        const int slot = i * 256 + tid;          // 0..511
        const int row = slot >> 2;               // 0..127
        const int seg = slot & 3;                // 16B segment (8 fp16)
        const uint32_t d = row * ROWB + seg * 16;
        const size_t gA = (size_t)(m0 + row) * EMBED + c * GBK + seg * 8;
        const size_t gB = (size_t)(n0 + row) * EMBED + c * GBK + seg * 8;
        cp16(st + 0 * MAT_BYTES + d, Ah + gA);
        if (TWO_PASS) cp16(st + 1 * MAT_BYTES + d, Al + gA);
        cp16(st + 2 * MAT_BYTES + d, B + gB);
    }
    CP_COMMIT();
}

// GEMM body: C = (Xh [+ Xl]) * W^T + bias  (fp32 accumulators)
// 256 threads, warp tile 32x64. B fragment loaded ONCE per n-pair and reused
// by both split passes (8 HMMA per ldsm4).
template <bool TWO_PASS>
static __device__ __forceinline__ void gemm_body(
    char* smem, int bx,
    const __half* __restrict__ Ah, const __half* __restrict__ Al,
    const __half* __restrict__ B, const float* __restrict__ bias,
    float* __restrict__ C)
{
    const uint32_t sb = smem_u32(smem);
    const int tid  = threadIdx.x;
    const int wid  = tid >> 5;
    const int lane = tid & 31;
    const int g    = lane >> 2;          // c-fragment row group 0..7
    const int tg   = lane & 3;           // c-fragment col pair 0..3

    const int n0 = (bx & 7) * 128;       // n fastest: CTAs sharing m0 reuse A in L2
    const int m0 = (bx >> 3) * 128;

    const int wm = wid & 3;              // 0..3 -> M offset
    const int wn = wid >> 2;             // 0..1 -> N offset

    const int grp = lane >> 3, lr8 = lane & 7;
    const uint32_t aoff = (uint32_t)((wm * 32 + (grp & 1) * 8 + lr8) * ROWB
                                     + (grp >> 1) * 16);
    const uint32_t boff = (uint32_t)((wn * 64 + (grp >> 1) * 8 + lr8) * ROWB
                                     + (grp & 1) * 16);

    float acc[2][8][4];
    #pragma unroll
    for (int mt = 0; mt < 2; mt++)
        #pragma unroll
        for (int nt = 0; nt < 8; nt++)
            #pragma unroll
            for (int r = 0; r < 4; r++) acc[mt][nt][r] = 0.f;

    load_chunk<TWO_PASS>(sb, 0, 0, m0, n0, Ah, Al, B, tid);

    for (int c = 0; c < G_NCH; c++) {
        const int buf = c & 1;
        if (c + 1 < G_NCH) {
            load_chunk<TWO_PASS>(sb, buf ^ 1, c + 1, m0, n0, Ah, Al, B, tid);
            CP_WAIT(1);
        } else {
            CP_WAIT(0);
        }
        __syncthreads();

        const uint32_t stAh = sb + buf * STAGE_B;
        const uint32_t stAl = stAh + MAT_BYTES;
        const uint32_t stB  = stAh + 2 * MAT_BYTES;

        #pragma unroll
        for (int step = 0; step < 2; step++) {
            const uint32_t so = step * 32;       // 16 fp16 = 32 B along k

            uint32_t ah[2][4], al[2][4];
            #pragma unroll
            for (int mt = 0; mt < 2; mt++) {
                ldsm4(ah[mt], stAh + aoff + mt * (16 * ROWB) + so);
                if (TWO_PASS)
                    ldsm4(al[mt], stAl + aoff + mt * (16 * ROWB) + so);
            }

            #pragma unroll
            for (int pr = 0; pr < 4; pr++) {     // n-row pairs: 2 n8 tiles each
                uint32_t b4[4];
                ldsm4(b4, stB + boff + pr * (16 * ROWB) + so);
                // hi pass (4 distinct accumulators)
                hmma(acc[0][2 * pr],     ah[0], b4[0], b4[1]);
                hmma(acc[0][2 * pr + 1], ah[0], b4[2], b4[3]);
                hmma(acc[1][2 * pr],     ah[1], b4[0], b4[1]);
                hmma(acc[1][2 * pr + 1], ah[1], b4[2], b4[3]);
                if (TWO_PASS) {
                    // lo pass reuses b4 (RAW distance 4)
                    hmma(acc[0][2 * pr],     al[0], b4[0], b4[1]);
                    hmma(acc[0][2 * pr + 1], al[0], b4[2], b4[3]);
                    hmma(acc[1][2 * pr],     al[1], b4[0], b4[1]);
                    hmma(acc[1][2 * pr + 1], al[1], b4[2], b4[3]);
                }
            }
        }
        __syncthreads();
    }

    #pragma unroll
    for (int mt = 0; mt < 2; mt++) {
        const int row = m0 + wm * 32 + mt * 16 + g;
        #pragma unroll
        for (int nt = 0; nt < 8; nt++) {
            const int col = n0 + wn * 64 + nt * 8 + 2 * tg;
            const float2 bv = *(const float2*)&bias[col];
            float2 v0 = make_float2(acc[mt][nt][0] + bv.x, acc[mt][nt][1] + bv.y);
            float2 v1 = make_float2(acc[mt][nt][2] + bv.x, acc[mt][nt][3] + bv.y);
            *(float2*)&C[(size_t)row * EMBED + col]       = v0;
            *(float2*)&C[(size_t)(row + 8) * EMBED + col] = v1;
        }
    }
}

// Gram body (256 threads): Gpart[c][bh][d][e] = sum_{s in chunk} Q.K (f32x2)
static __device__ __forceinline__ void gram_body(char* smem, int bh, int chunk)
{
    float (*Qs)[64] = (float(*)[64])smem;
    float (*Ks)[64] = (float(*)[64])(smem + 64 * 64 * 4);

    const int b = bh >> 4, h = bh & 15;
    const float* Q = g_QKV[0];
    const float* K = g_QKV[1];
    const size_t base = ((size_t)b * SEQ + (size_t)chunk * SCHUNK) * EMBED + h * DK;

    const int tid = threadIdx.x;
    const int tx = tid & 15, ty = tid >> 4;
    const int lr = tid >> 4, lc4 = (tid & 15) << 2;

    unsigned long long c2[4][2];
    #pragma unroll
    for (int i = 0; i < 4; i++) { c2[i][0] = 0ull; c2[i][1] = 0ull; }

    for (int st = 0; st < SCHUNK / 64; st++) {
        #pragma unroll
        for (int rr = 0; rr < 64; rr += 16) {
            const int s = rr + lr;
            const size_t gg = base + (size_t)(st * 64 + s) * EMBED + lc4;
            *(float4*)&Qs[s][lc4] = *(const float4*)(Q + gg);
            *(float4*)&Ks[s][lc4] = *(const float4*)(K + gg);
        }
        __syncthreads();

        #pragma unroll 8
        for (int ss = 0; ss < 64; ss++) {
            float4 q4 = *(const float4*)&Qs[ss][ty * 4];
            ulonglong2 k2 = *(const ulonglong2*)&Ks[ss][tx * 4];
            float qv[4] = {q4.x, q4.y, q4.z, q4.w};
            #pragma unroll
            for (int i = 0; i < 4; i++) {
                unsigned long long ad = dup2(qv[i]);
                ffma2(c2[i][0], ad, k2.x);
                ffma2(c2[i][1], ad, k2.y);
            }
        }
        __syncthreads();
    }

    float* gp = g_Gpart + ((size_t)chunk * BHEADS + bh) * DK * DK;
    #pragma unroll
    for (int i = 0; i < 4; i++) {
        const int d = ty * 4 + i;
        *(float4*)&gp[d * DK + tx * 4] =
            make_float4(lo2(c2[i][0]), hi2(c2[i][0]), lo2(c2[i][1]), hi2(c2[i][1]));
    }
}

// ---------------------------------------------------------------------------
// Kernel A: fused prep — x hi/lo split + 3x W fp16 convert, one launch.
// ---------------------------------------------------------------------------
#define XB  ((MTOK * EMBED) / 1024)     /* 32768 blocks */
#define WB  ((EMBED * EMBED) / 1024)    /* 1024 blocks per W */

__global__ __launch_bounds__(256)
void prep_kernel(const float* __restrict__ x,
                 const float* __restrict__ Wq, const float* __restrict__ Wk,
                 const float* __restrict__ Wv,
                 __half* __restrict__ xh, __half* __restrict__ xl,
                 __half* __restrict__ w0, __half* __restrict__ w1,
                 __half* __restrict__ w2)
{
    const int bx = blockIdx.x;
    if (bx < XB) {
        const int i = (bx * 256 + threadIdx.x) * 4;
        float4 v = *(const float4*)(x + i);
        __half h0 = __float2half_rn(v.x), h1 = __float2half_rn(v.y);
        __half h2 = __float2half_rn(v.z), h3 = __float2half_rn(v.w);
        __half l0 = __float2half_rn(v.x - __half2float(h0));
        __half l1 = __float2half_rn(v.y - __half2float(h1));
        __half l2 = __float2half_rn(v.z - __half2float(h2));
        __half l3 = __float2half_rn(v.w - __half2float(h3));
        __half2 hp0 = {h0, h1}, hp1 = {h2, h3};
        __half2 lp0 = {l0, l1}, lp1 = {l2, l3};
        *(__half2*)(xh + i)     = hp0;
        *(__half2*)(xh + i + 2) = hp1;
        *(__half2*)(xl + i)     = lp0;
        *(__half2*)(xl + i + 2) = lp1;
    } else {
        const int wi = (bx - XB) / WB;             // 0..2
        const int wb = (bx - XB) - wi * WB;
        const float* src = (wi == 0) ? Wq : (wi == 1) ? Wk : Wv;
        __half* dst = (wi == 0) ? w0 : (wi == 1) ? w1 : w2;
        const int i = (wb * 256 + threadIdx.x) * 4;
        float4 v = *(const float4*)(src + i);
        __half2 p0 = {__float2half_rn(v.x), __float2half_rn(v.y)};
        __half2 p1 = {__float2half_rn(v.z), __float2half_rn(v.w)};
        *(__half2*)(dst + i)     = p0;
        *(__half2*)(dst + i + 2) = p1;
    }
}

// ---------------------------------------------------------------------------
// Kernel B: standalone projection GEMM (Q and K: two-pass)
// ---------------------------------------------------------------------------
__global__ __launch_bounds__(256, 2)
void gemm_split_kernel(const __half* __restrict__ Ah,
                       const __half* __restrict__ Al,
                       const __half* __restrict__ B,
                       const float* __restrict__ bias,
                       float* __restrict__ C)
{
    extern __shared__ char smem[];
    gemm_body<true>(smem, blockIdx.x, Ah, Al, B, bias, C);
}

// ---------------------------------------------------------------------------
// Kernel C: FUSED V-projection GEMM (single-pass fp16) + gram, interleaved 2:1
// ---------------------------------------------------------------------------
__global__ __launch_bounds__(256, 2)
void vgemm_gram_kernel(const __half* __restrict__ Ah,
                       const __half* __restrict__ Al,
                       const __half* __restrict__ B,
                       const float* __restrict__ bias,
                       float* __restrict__ C)
{
    extern __shared__ char smem[];
    const int bx = blockIdx.x;
    const int r = bx % 3;
    if (r < 2) {
        const int gemm_id = (bx / 3) * 2 + r;        // 0..2047
        gemm_body<false>(smem, gemm_id, Ah, Al, B, bias, C);
    } else {
        const int gram_id = bx / 3;                  // 0..1023
        gram_body(smem, gram_id & (BHEADS - 1), gram_id >> 7);
    }
}

// ---------------------------------------------------------------------------
// Kernel D: reduce partials + softmax; write attn transposed At[e][d]
// ---------------------------------------------------------------------------
__global__ __launch_bounds__(256)
void softmax_kernel()
{
    const int gwarp = (blockIdx.x * blockDim.x + threadIdx.x) >> 5;
    const int lane = threadIdx.x & 31;
    const int bh = gwarp >> 6;
    const int d = gwarp & 63;

    float g0 = 0.f, g1 = 0.f;
    #pragma unroll
    for (int c = 0; c < NCHUNK; c++) {
        const float* gp = g_Gpart + (((size_t)c * BHEADS + bh) * DK + d) * DK;
        g0 += gp[lane];
        g1 += gp[lane + 32];
    }
    g0 *= 0.125f; g1 *= 0.125f;

    float m = fmaxf(g0, g1);
    #pragma unroll
    for (int o = 16; o > 0; o >>= 1) m = fmaxf(m, __shfl_xor_sync(0xffffffffu, m, o));
    float e0 = expf(g0 - m), e1 = expf(g1 - m);
    float s = e0 + e1;
    #pragma unroll
    for (int o = 16; o > 0; o >>= 1) s += __shfl_xor_sync(0xffffffffu, s, o);
    const float inv = 1.0f / s;

    float* at = g_At + (size_t)bh * DK * DK;
    at[lane * DK + d]        = e0 * inv;
    at[(lane + 32) * DK + d] = e1 * inv;
}

// ---------------------------------------------------------------------------
// Kernel E: output mix  out[m, h*64+d] = sum_e attn[bh][d][e] * V[m, h*64+e]
// ---------------------------------------------------------------------------
__global__ __launch_bounds__(256, 2)
void out_kernel(float* __restrict__ OUT)
{
    __shared__ float Am[64][64];
    __shared__ float Vt[64][65];

    const int m0 = blockIdx.x * 64;
    const int h  = blockIdx.y;
    const int b  = m0 >> 12;
    const int bh = b * NHEADS + h;
    const float* V = g_QKV[2];

    const int tid = threadIdx.x;
    const int tx = tid & 15, ty = tid >> 4;
    const int lr = tid >> 4, lc4 = (tid & 15) << 2;

    const float* at = g_At + (size_t)bh * DK * DK;
    #pragma unroll
    for (int rr = 0; rr < 64; rr += 16)
        *(float4*)&Am[rr + lr][lc4] = *(const float4*)&at[(rr + lr) * DK + lc4];

    #pragma unroll
    for (int rr = 0; rr < 64; rr += 16) {
        const int s = rr + lr;
        float4 v = *(const float4*)(V + (size_t)(m0 + s) * EMBED + h * DK + lc4);
        Vt[lc4 + 0][s] = v.x;
        Vt[lc4 + 1][s] = v.y;
        Vt[lc4 + 2][s] = v.z;
        Vt[lc4 + 3][s] = v.w;
    }
    __syncthreads();

    unsigned long long o2[4][2];
    #pragma unroll
    for (int i = 0; i < 4; i++) { o2[i][0] = 0ull; o2[i][1] = 0ull; }

    #pragma unroll 8
    for (int ee = 0; ee < 64; ee++) {
        ulonglong2 ap = *(const ulonglong2*)&Am[ee][tx * 4];
        #pragma unroll
        for (int si = 0; si < 4; si++) {
            unsigned long long vd = dup2(Vt[ee][ty * 4 + si]);
            ffma2(o2[si][0], vd, ap.x);
            ffma2(o2[si][1], vd, ap.y);
        }
    }

    #pragma unroll
    for (int si = 0; si < 4; si++) {
        const int m = m0 + ty * 4 + si;
        *(float4*)&OUT[(size_t)m * EMBED + h * DK + tx * 4] =
            make_float4(lo2(o2[si][0]), hi2(o2[si][0]),
                        lo2(o2[si][1]), hi2(o2[si][1]));
    }
}

// ---------------------------------------------------------------------------
// Launch
// ---------------------------------------------------------------------------
extern "C" void kernel_launch(void* const* d_in, const int* in_sizes, int n_in,
                              void* d_out, int out_size)
{
    const float* x  = (const float*)d_in[0];
    const float* Wq = (const float*)d_in[1];
    const float* bq = (const float*)d_in[2];
    const float* Wk = (const float*)d_in[3];
    const float* bk = (const float*)d_in[4];
    const float* Wv = (const float*)d_in[5];
    const float* bv = (const float*)d_in[6];
    float* out = (float*)d_out;

    cudaFuncSetAttribute(gemm_split_kernel,
                         cudaFuncAttributeMaxDynamicSharedMemorySize, G_SMEM);
    cudaFuncSetAttribute(vgemm_gram_kernel,
                         cudaFuncAttributeMaxDynamicSharedMemorySize, G_SMEM);

    __half *xh, *xl, *wb;
    cudaGetSymbolAddress((void**)&xh, g_xh);
    cudaGetSymbolAddress((void**)&xl, g_xl);
    cudaGetSymbolAddress((void**)&wb, g_w);
    float* qkv;
    cudaGetSymbolAddress((void**)&qkv, g_QKV);

    __half* w0 = wb;
    __half* w1 = wb + EMBED * EMBED;
    __half* w2 = wb + 2 * EMBED * EMBED;

    // 1) fused conversions
    prep_kernel<<<XB + 3 * WB, 256>>>(x, Wq, Wk, Wv, xh, xl, w0, w1, w2);

    // 2) Q and K projections (two-pass split, B-fragment reuse)
    gemm_split_kernel<<<GEMM_BLOCKS, 256, G_SMEM>>>(xh, xl, w0, bq,
                                                    qkv + 0ll * MTOK * EMBED);
    gemm_split_kernel<<<GEMM_BLOCKS, 256, G_SMEM>>>(xh, xl, w1, bk,
                                                    qkv + 1ll * MTOK * EMBED);

    // 3) fused: V projection (single-pass fp16, tensor pipe) + gram (fma pipe)
    vgemm_gram_kernel<<<GEMM_BLOCKS + GRAM_BLOCKS, 256, G_SMEM>>>(
        xh, xl, w2, bv, qkv + 2ll * MTOK * EMBED);

    // 4) softmax + output mix
    softmax_kernel<<<(BHEADS * DK) / 8, 256>>>();
    out_kernel<<<dim3(MTOK / 64, NHEADS), 256>>>(out);
}

// round 14
// speedup vs baseline: 1.3624x; 1.1194x over previous
#include <cuda_runtime.h>
#include <cuda_bf16.h>
#include <cuda_fp16.h>
#include <cstdint>

#define EMBED   1024
#define NHEADS  16
#define DK      64
#define BATCH   8
#define SEQ     4096
#define MTOK    (BATCH * SEQ)      /* 32768 tokens */
#define BHEADS  (BATCH * NHEADS)   /* 128 head-instances */
#define NCHUNK  8
#define SCHUNK  (SEQ / NCHUNK)     /* 512 */

// ---------------------------------------------------------------------------
// Scratch (__device__ globals: the sanctioned no-alloc workaround)
// ---------------------------------------------------------------------------
__device__ float g_QKV[3][MTOK * EMBED];                     // fp32 Q,K,V
__device__ float g_Gpart[NCHUNK * BHEADS * DK * DK];         // gram partials
__device__ float g_At[BHEADS * DK * DK];                     // attn transposed [e][d]
__device__ __half g_xh[MTOK * EMBED];                        // x fp16 hi
__device__ __half g_xl[MTOK * EMBED];                        // x fp16 lo (residual)
__device__ __half g_w[3][EMBED * EMBED];                     // W fp16 (q,k,v)

// ---------------------------------------------------------------------------
// helpers
// ---------------------------------------------------------------------------
static __device__ __forceinline__ uint32_t smem_u32(const void* p) {
    uint32_t a;
    asm("{ .reg .u64 t; cvta.to.shared.u64 t, %1; cvt.u32.u64 %0, t; }"
        : "=r"(a) : "l"(p));
    return a;
}
static __device__ __forceinline__ void cp16(uint32_t dst, const void* src) {
    asm volatile("cp.async.cg.shared.global [%0], [%1], 16;" :: "r"(dst), "l"(src));
}
#define CP_COMMIT()  asm volatile("cp.async.commit_group;" ::: "memory")
#define CP_WAIT(n)   asm volatile("cp.async.wait_group %0;" :: "n"(n) : "memory")

// mma.sync m16n8k16 row.col f32.f16.f16.f32 (baseline sm_80+ path)
static __device__ __forceinline__ void hmma(float* c, const uint32_t* a,
                                            uint32_t b0, uint32_t b1) {
    asm volatile(
        "mma.sync.aligned.m16n8k16.row.col.f32.f16.f16.f32 "
        "{%0,%1,%2,%3}, {%4,%5,%6,%7}, {%8,%9}, {%0,%1,%2,%3};"
        : "+f"(c[0]), "+f"(c[1]), "+f"(c[2]), "+f"(c[3])
        : "r"(a[0]), "r"(a[1]), "r"(a[2]), "r"(a[3]), "r"(b0), "r"(b1));
}
// ldmatrix x4: fills 4 fragment regs from 4 8x8 b16 tiles (lane-group addressed)
static __device__ __forceinline__ void ldsm4(uint32_t* r, uint32_t addr) {
    asm volatile("ldmatrix.sync.aligned.m8n8.x4.shared.b16 {%0,%1,%2,%3}, [%4];"
                 : "=r"(r[0]), "=r"(r[1]), "=r"(r[2]), "=r"(r[3]) : "r"(addr));
}

// packed fp32x2 helpers (for the fp32 attention kernels)
__device__ __forceinline__ void ffma2(unsigned long long &d, unsigned long long a,
                                      unsigned long long b) {
    asm("fma.rn.f32x2 %0, %1, %2, %0;" : "+l"(d) : "l"(a), "l"(b));
}
__device__ __forceinline__ unsigned long long dup2(float x) {
    unsigned long long r; unsigned xi = __float_as_uint(x);
    asm("mov.b64 %0, {%1, %1};" : "=l"(r) : "r"(xi));
    return r;
}
__device__ __forceinline__ float lo2(unsigned long long v) {
    return __uint_as_float((unsigned)(v & 0xffffffffull));
}
__device__ __forceinline__ float hi2(unsigned long long v) {
    return __uint_as_float((unsigned)(v >> 32));
}

// ---------------------------------------------------------------------------
// GEMM configuration (256 threads, 8 warps 4Mx2N, warp tile 32x64)
// ---------------------------------------------------------------------------
#define GBK        32
#define G_NCH      (EMBED / GBK)        /* 32 chunks */
#define PADW       40                   /* fp16 per padded row */
#define ROWB       (PADW * 2)           /* 80 bytes per row */
#define MAT_BYTES  (128 * ROWB)         /* 10240 */
#define STAGE_B    (3 * MAT_BYTES)      /* 30720 */
#define G_SMEM     (2 * STAGE_B)        /* 61440 */
#define GEMM_BLOCKS (EMBED / 128 * (MTOK / 128))   /* 8 * 256 = 2048 */
#define GRAM_BLOCKS (BHEADS * NCHUNK)              /* 1024 */

template <bool TWO_PASS>
static __device__ __forceinline__ void load_chunk(
    uint32_t sb, int buf, int c, int m0, int n0,
    const __half* __restrict__ Ah, const __half* __restrict__ Al,
    const __half* __restrict__ B, int tid)
{
    const uint32_t st = sb + buf * STAGE_B;
    #pragma unroll
    for (int i = 0; i < 2; i++) {
        const int slot = i * 256 + tid;          // 0..511
        const int row = slot >> 2;               // 0..127
        const int seg = slot & 3;                // 16B segment (8 fp16)
        const uint32_t d = row * ROWB + seg * 16;
        const size_t gA = (size_t)(m0 + row) * EMBED + c * GBK + seg * 8;
        const size_t gB = (size_t)(n0 + row) * EMBED + c * GBK + seg * 8;
        cp16(st + 0 * MAT_BYTES + d, Ah + gA);
        if (TWO_PASS) cp16(st + 1 * MAT_BYTES + d, Al + gA);
        cp16(st + 2 * MAT_BYTES + d, B + gB);
    }
    CP_COMMIT();
}

// GEMM body: C = (Xh [+ Xl]) * W^T + bias  (fp32 accumulators)
// 256 threads, warp tile 32x64. B fragment loaded ONCE per n-pair and reused
// by both split passes (8 HMMA per ldsm4).
template <bool TWO_PASS>
static __device__ __forceinline__ void gemm_body(
    char* smem, int bx,
    const __half* __restrict__ Ah, const __half* __restrict__ Al,
    const __half* __restrict__ B, const float* __restrict__ bias,
    float* __restrict__ C)
{
    const uint32_t sb = smem_u32(smem);
    const int tid  = threadIdx.x;
    const int wid  = tid >> 5;
    const int lane = tid & 31;
    const int g    = lane >> 2;          // c-fragment row group 0..7
    const int tg   = lane & 3;           // c-fragment col pair 0..3

    const int n0 = (bx & 7) * 128;       // n fastest: CTAs sharing m0 reuse A in L2
    const int m0 = (bx >> 3) * 128;

    const int wm = wid & 3;              // 0..3 -> M offset
    const int wn = wid >> 2;             // 0..1 -> N offset

    const int grp = lane >> 3, lr8 = lane & 7;
    const uint32_t aoff = (uint32_t)((wm * 32 + (grp & 1) * 8 + lr8) * ROWB
                                     + (grp >> 1) * 16);
    const uint32_t boff = (uint32_t)((wn * 64 + (grp >> 1) * 8 + lr8) * ROWB
                                     + (grp & 1) * 16);

    float acc[2][8][4];
    #pragma unroll
    for (int mt = 0; mt < 2; mt++)
        #pragma unroll
        for (int nt = 0; nt < 8; nt++)
            #pragma unroll
            for (int r = 0; r < 4; r++) acc[mt][nt][r] = 0.f;

    load_chunk<TWO_PASS>(sb, 0, 0, m0, n0, Ah, Al, B, tid);

    for (int c = 0; c < G_NCH; c++) {
        const int buf = c & 1;
        if (c + 1 < G_NCH) {
            load_chunk<TWO_PASS>(sb, buf ^ 1, c + 1, m0, n0, Ah, Al, B, tid);
            CP_WAIT(1);
        } else {
            CP_WAIT(0);
        }
        __syncthreads();

        const uint32_t stAh = sb + buf * STAGE_B;
        const uint32_t stAl = stAh + MAT_BYTES;
        const uint32_t stB  = stAh + 2 * MAT_BYTES;

        #pragma unroll
        for (int step = 0; step < 2; step++) {
            const uint32_t so = step * 32;       // 16 fp16 = 32 B along k

            uint32_t ah[2][4], al[2][4];
            #pragma unroll
            for (int mt = 0; mt < 2; mt++) {
                ldsm4(ah[mt], stAh + aoff + mt * (16 * ROWB) + so);
                if (TWO_PASS)
                    ldsm4(al[mt], stAl + aoff + mt * (16 * ROWB) + so);
            }

            #pragma unroll
            for (int pr = 0; pr < 4; pr++) {     // n-row pairs: 2 n8 tiles each
                uint32_t b4[4];
                ldsm4(b4, stB + boff + pr * (16 * ROWB) + so);
                // hi pass (4 distinct accumulators)
                hmma(acc[0][2 * pr],     ah[0], b4[0], b4[1]);
                hmma(acc[0][2 * pr + 1], ah[0], b4[2], b4[3]);
                hmma(acc[1][2 * pr],     ah[1], b4[0], b4[1]);
                hmma(acc[1][2 * pr + 1], ah[1], b4[2], b4[3]);
                if (TWO_PASS) {
                    // lo pass reuses b4 (RAW distance 4)
                    hmma(acc[0][2 * pr],     al[0], b4[0], b4[1]);
                    hmma(acc[0][2 * pr + 1], al[0], b4[2], b4[3]);
                    hmma(acc[1][2 * pr],     al[1], b4[0], b4[1]);
                    hmma(acc[1][2 * pr + 1], al[1], b4[2], b4[3]);
                }
            }
        }
        __syncthreads();
    }

    #pragma unroll
    for (int mt = 0; mt < 2; mt++) {
        const int row = m0 + wm * 32 + mt * 16 + g;
        #pragma unroll
        for (int nt = 0; nt < 8; nt++) {
            const int col = n0 + wn * 64 + nt * 8 + 2 * tg;
            const float2 bv = *(const float2*)&bias[col];
            float2 v0 = make_float2(acc[mt][nt][0] + bv.x, acc[mt][nt][1] + bv.y);
            float2 v1 = make_float2(acc[mt][nt][2] + bv.x, acc[mt][nt][3] + bv.y);
            *(float2*)&C[(size_t)row * EMBED + col]       = v0;
            *(float2*)&C[(size_t)(row + 8) * EMBED + col] = v1;
        }
    }
}

// Gram body (256 threads): Gpart[c][bh][d][e] = sum_{s in chunk} Q.K (f32x2)
static __device__ __forceinline__ void gram_body(char* smem, int bh, int chunk)
{
    float (*Qs)[64] = (float(*)[64])smem;
    float (*Ks)[64] = (float(*)[64])(smem + 64 * 64 * 4);

    const int b = bh >> 4, h = bh & 15;
    const float* Q = g_QKV[0];
    const float* K = g_QKV[1];
    const size_t base = ((size_t)b * SEQ + (size_t)chunk * SCHUNK) * EMBED + h * DK;

    const int tid = threadIdx.x;
    const int tx = tid & 15, ty = tid >> 4;
    const int lr = tid >> 4, lc4 = (tid & 15) << 2;

    unsigned long long c2[4][2];
    #pragma unroll
    for (int i = 0; i < 4; i++) { c2[i][0] = 0ull; c2[i][1] = 0ull; }

    for (int st = 0; st < SCHUNK / 64; st++) {
        #pragma unroll
        for (int rr = 0; rr < 64; rr += 16) {
            const int s = rr + lr;
            const size_t gg = base + (size_t)(st * 64 + s) * EMBED + lc4;
            *(float4*)&Qs[s][lc4] = *(const float4*)(Q + gg);
            *(float4*)&Ks[s][lc4] = *(const float4*)(K + gg);
        }
        __syncthreads();

        #pragma unroll 8
        for (int ss = 0; ss < 64; ss++) {
            float4 q4 = *(const float4*)&Qs[ss][ty * 4];
            ulonglong2 k2 = *(const ulonglong2*)&Ks[ss][tx * 4];
            float qv[4] = {q4.x, q4.y, q4.z, q4.w};
            #pragma unroll
            for (int i = 0; i < 4; i++) {
                unsigned long long ad = dup2(qv[i]);
                ffma2(c2[i][0], ad, k2.x);
                ffma2(c2[i][1], ad, k2.y);
            }
        }
        __syncthreads();
    }

    float* gp = g_Gpart + ((size_t)chunk * BHEADS + bh) * DK * DK;
    #pragma unroll
    for (int i = 0; i < 4; i++) {
        const int d = ty * 4 + i;
        *(float4*)&gp[d * DK + tx * 4] =
            make_float4(lo2(c2[i][0]), hi2(c2[i][0]), lo2(c2[i][1]), hi2(c2[i][1]));
    }
}

// ---------------------------------------------------------------------------
// Kernel A: fused prep — x hi/lo split + 3x W fp16 convert, one launch.
// ---------------------------------------------------------------------------
#define XB  ((MTOK * EMBED) / 1024)     /* 32768 blocks */
#define WB  ((EMBED * EMBED) / 1024)    /* 1024 blocks per W */

__global__ __launch_bounds__(256)
void prep_kernel(const float* __restrict__ x,
                 const float* __restrict__ Wq, const float* __restrict__ Wk,
                 const float* __restrict__ Wv,
                 __half* __restrict__ xh, __half* __restrict__ xl,
                 __half* __restrict__ w0, __half* __restrict__ w1,
                 __half* __restrict__ w2)
{
    const int bx = blockIdx.x;
    if (bx < XB) {
        const int i = (bx * 256 + threadIdx.x) * 4;
        float4 v = *(const float4*)(x + i);
        __half h0 = __float2half_rn(v.x), h1 = __float2half_rn(v.y);
        __half h2 = __float2half_rn(v.z), h3 = __float2half_rn(v.w);
        __half l0 = __float2half_rn(v.x - __half2float(h0));
        __half l1 = __float2half_rn(v.y - __half2float(h1));
        __half l2 = __float2half_rn(v.z - __half2float(h2));
        __half l3 = __float2half_rn(v.w - __half2float(h3));
        __half2 hp0 = {h0, h1}, hp1 = {h2, h3};
        __half2 lp0 = {l0, l1}, lp1 = {l2, l3};
        *(__half2*)(xh + i)     = hp0;
        *(__half2*)(xh + i + 2) = hp1;
        *(__half2*)(xl + i)     = lp0;
        *(__half2*)(xl + i + 2) = lp1;
    } else {
        const int wi = (bx - XB) / WB;             // 0..2
        const int wb = (bx - XB) - wi * WB;
        const float* src = (wi == 0) ? Wq : (wi == 1) ? Wk : Wv;
        __half* dst = (wi == 0) ? w0 : (wi == 1) ? w1 : w2;
        const int i = (wb * 256 + threadIdx.x) * 4;
        float4 v = *(const float4*)(src + i);
        __half2 p0 = {__float2half_rn(v.x), __float2half_rn(v.y)};
        __half2 p1 = {__float2half_rn(v.z), __float2half_rn(v.w)};
        *(__half2*)(dst + i)     = p0;
        *(__half2*)(dst + i + 2) = p1;
    }
}

// ---------------------------------------------------------------------------
// Kernel B1: two-pass projection GEMM (K: full hi/lo split)
// ---------------------------------------------------------------------------
__global__ __launch_bounds__(256, 2)
void gemm_split_kernel(const __half* __restrict__ Ah,
                       const __half* __restrict__ Al,
                       const __half* __restrict__ B,
                       const float* __restrict__ bias,
                       float* __restrict__ C)
{
    extern __shared__ char smem[];
    gemm_body<true>(smem, blockIdx.x, Ah, Al, B, bias, C);
}

// ---------------------------------------------------------------------------
// Kernel B2: single-pass projection GEMM (Q: fp16 only; error budget spent)
// ---------------------------------------------------------------------------
__global__ __launch_bounds__(256, 2)
void gemm_single_kernel(const __half* __restrict__ Ah,
                        const __half* __restrict__ B,
                        const float* __restrict__ bias,
                        float* __restrict__ C)
{
    extern __shared__ char smem[];
    gemm_body<false>(smem, blockIdx.x, Ah, nullptr, B, bias, C);
}

// ---------------------------------------------------------------------------
// Kernel C: FUSED V-projection GEMM (single-pass fp16) + gram, interleaved 2:1
// ---------------------------------------------------------------------------
__global__ __launch_bounds__(256, 2)
void vgemm_gram_kernel(const __half* __restrict__ Ah,
                       const __half* __restrict__ B,
                       const float* __restrict__ bias,
                       float* __restrict__ C)
{
    extern __shared__ char smem[];
    const int bx = blockIdx.x;
    const int r = bx % 3;
    if (r < 2) {
        const int gemm_id = (bx / 3) * 2 + r;        // 0..2047
        gemm_body<false>(smem, gemm_id, Ah, nullptr, B, bias, C);
    } else {
        const int gram_id = bx / 3;                  // 0..1023
        gram_body(smem, gram_id & (BHEADS - 1), gram_id >> 7);
    }
}

// ---------------------------------------------------------------------------
// Kernel D: reduce partials + softmax; write attn transposed At[e][d]
// ---------------------------------------------------------------------------
__global__ __launch_bounds__(256)
void softmax_kernel()
{
    const int gwarp = (blockIdx.x * blockDim.x + threadIdx.x) >> 5;
    const int lane = threadIdx.x & 31;
    const int bh = gwarp >> 6;
    const int d = gwarp & 63;

    float g0 = 0.f, g1 = 0.f;
    #pragma unroll
    for (int c = 0; c < NCHUNK; c++) {
        const float* gp = g_Gpart + (((size_t)c * BHEADS + bh) * DK + d) * DK;
        g0 += gp[lane];
        g1 += gp[lane + 32];
    }
    g0 *= 0.125f; g1 *= 0.125f;

    float m = fmaxf(g0, g1);
    #pragma unroll
    for (int o = 16; o > 0; o >>= 1) m = fmaxf(m, __shfl_xor_sync(0xffffffffu, m, o));
    float e0 = expf(g0 - m), e1 = expf(g1 - m);
    float s = e0 + e1;
    #pragma unroll
    for (int o = 16; o > 0; o >>= 1) s += __shfl_xor_sync(0xffffffffu, s, o);
    const float inv = 1.0f / s;

    float* at = g_At + (size_t)bh * DK * DK;
    at[lane * DK + d]        = e0 * inv;
    at[(lane + 32) * DK + d] = e1 * inv;
}

// ---------------------------------------------------------------------------
// Kernel E: output mix  out[m, h*64+d] = sum_e attn[bh][d][e] * V[m, h*64+e]
// ---------------------------------------------------------------------------
__global__ __launch_bounds__(256, 2)
void out_kernel(float* __restrict__ OUT)
{
    __shared__ float Am[64][64];
    __shared__ float Vt[64][65];

    const int m0 = blockIdx.x * 64;
    const int h  = blockIdx.y;
    const int b  = m0 >> 12;
    const int bh = b * NHEADS + h;
    const float* V = g_QKV[2];

    const int tid = threadIdx.x;
    const int tx = tid & 15, ty = tid >> 4;
    const int lr = tid >> 4, lc4 = (tid & 15) << 2;

    const float* at = g_At + (size_t)bh * DK * DK;
    #pragma unroll
    for (int rr = 0; rr < 64; rr += 16)
        *(float4*)&Am[rr + lr][lc4] = *(const float4*)&at[(rr + lr) * DK + lc4];

    #pragma unroll
    for (int rr = 0; rr < 64; rr += 16) {
        const int s = rr + lr;
        float4 v = *(const float4*)(V + (size_t)(m0 + s) * EMBED + h * DK + lc4);
        Vt[lc4 + 0][s] = v.x;
        Vt[lc4 + 1][s] = v.y;
        Vt[lc4 + 2][s] = v.z;
        Vt[lc4 + 3][s] = v.w;
    }
    __syncthreads();

    unsigned long long o2[4][2];
    #pragma unroll
    for (int i = 0; i < 4; i++) { o2[i][0] = 0ull; o2[i][1] = 0ull; }

    #pragma unroll 8
    for (int ee = 0; ee < 64; ee++) {
        ulonglong2 ap = *(const ulonglong2*)&Am[ee][tx * 4];
        #pragma unroll
        for (int si = 0; si < 4; si++) {
            unsigned long long vd = dup2(Vt[ee][ty * 4 + si]);
            ffma2(o2[si][0], vd, ap.x);
            ffma2(o2[si][1], vd, ap.y);
        }
    }

    #pragma unroll
    for (int si = 0; si < 4; si++) {
        const int m = m0 + ty * 4 + si;
        *(float4*)&OUT[(size_t)m * EMBED + h * DK + tx * 4] =
            make_float4(lo2(o2[si][0]), hi2(o2[si][0]),
                        lo2(o2[si][1]), hi2(o2[si][1]));
    }
}

// ---------------------------------------------------------------------------
// Launch
// ---------------------------------------------------------------------------
extern "C" void kernel_launch(void* const* d_in, const int* in_sizes, int n_in,
                              void* d_out, int out_size)
{
    const float* x  = (const float*)d_in[0];
    const float* Wq = (const float*)d_in[1];
    const float* bq = (const float*)d_in[2];
    const float* Wk = (const float*)d_in[3];
    const float* bk = (const float*)d_in[4];
    const float* Wv = (const float*)d_in[5];
    const float* bv = (const float*)d_in[6];
    float* out = (float*)d_out;

    cudaFuncSetAttribute(gemm_split_kernel,
                         cudaFuncAttributeMaxDynamicSharedMemorySize, G_SMEM);
    cudaFuncSetAttribute(gemm_single_kernel,
                         cudaFuncAttributeMaxDynamicSharedMemorySize, G_SMEM);
    cudaFuncSetAttribute(vgemm_gram_kernel,
                         cudaFuncAttributeMaxDynamicSharedMemorySize, G_SMEM);

    __half *xh, *xl, *wb;
    cudaGetSymbolAddress((void**)&xh, g_xh);
    cudaGetSymbolAddress((void**)&xl, g_xl);
    cudaGetSymbolAddress((void**)&wb, g_w);
    float* qkv;
    cudaGetSymbolAddress((void**)&qkv, g_QKV);

    __half* w0 = wb;
    __half* w1 = wb + EMBED * EMBED;
    __half* w2 = wb + 2 * EMBED * EMBED;

    // 1) fused conversions
    prep_kernel<<<XB + 3 * WB, 256>>>(x, Wq, Wk, Wv, xh, xl, w0, w1, w2);

    // 2) Q projection: single-pass fp16 (error budget spent here);
    //    K projection: two-pass hi/lo split (keeps gram precision)
    gemm_single_kernel<<<GEMM_BLOCKS, 256, G_SMEM>>>(xh, w0, bq,
                                                     qkv + 0ll * MTOK * EMBED);
    gemm_split_kernel<<<GEMM_BLOCKS, 256, G_SMEM>>>(xh, xl, w1, bk,
                                                    qkv + 1ll * MTOK * EMBED);

    // 3) fused: V projection (single-pass fp16, tensor pipe) + gram (fma pipe)
    vgemm_gram_kernel<<<GEMM_BLOCKS + GRAM_BLOCKS, 256, G_SMEM>>>(
        xh, w2, bv, qkv + 2ll * MTOK * EMBED);

    // 4) softmax + output mix
    softmax_kernel<<<(BHEADS * DK) / 8, 256>>>();
    out_kernel<<<dim3(MTOK / 64, NHEADS), 256>>>(out);
}

// round 15
// speedup vs baseline: 1.5913x; 1.1681x over previous
#include <cuda_runtime.h>
#include <cuda_bf16.h>
#include <cuda_fp16.h>
#include <cstdint>

#define EMBED   1024
#define NHEADS  16
#define DK      64
#define BATCH   8
#define SEQ     4096
#define MTOK    (BATCH * SEQ)      /* 32768 tokens */
#define BHEADS  (BATCH * NHEADS)   /* 128 head-instances */
#define NCHUNK  8
#define SCHUNK  (SEQ / NCHUNK)     /* 512 */

// ---------------------------------------------------------------------------
// Scratch (__device__ globals: the sanctioned no-alloc workaround)
// ---------------------------------------------------------------------------
__device__ float g_QKV[3][MTOK * EMBED];                     // fp32 Q,K,V
__device__ float g_Gpart[NCHUNK * BHEADS * DK * DK];         // gram partials
__device__ float g_At[BHEADS * DK * DK];                     // attn transposed [e][d]
__device__ __half g_xh[MTOK * EMBED];                        // x fp16
__device__ __half g_w[3][EMBED * EMBED];                     // W fp16 (q,k,v)

// ---------------------------------------------------------------------------
// helpers
// ---------------------------------------------------------------------------
static __device__ __forceinline__ uint32_t smem_u32(const void* p) {
    uint32_t a;
    asm("{ .reg .u64 t; cvta.to.shared.u64 t, %1; cvt.u32.u64 %0, t; }"
        : "=r"(a) : "l"(p));
    return a;
}
static __device__ __forceinline__ void cp16(uint32_t dst, const void* src) {
    asm volatile("cp.async.cg.shared.global [%0], [%1], 16;" :: "r"(dst), "l"(src));
}
#define CP_COMMIT()  asm volatile("cp.async.commit_group;" ::: "memory")
#define CP_WAIT(n)   asm volatile("cp.async.wait_group %0;" :: "n"(n) : "memory")

// mma.sync m16n8k16 row.col f32.f16.f16.f32 (baseline sm_80+ path)
static __device__ __forceinline__ void hmma(float* c, const uint32_t* a,
                                            uint32_t b0, uint32_t b1) {
    asm volatile(
        "mma.sync.aligned.m16n8k16.row.col.f32.f16.f16.f32 "
        "{%0,%1,%2,%3}, {%4,%5,%6,%7}, {%8,%9}, {%0,%1,%2,%3};"
        : "+f"(c[0]), "+f"(c[1]), "+f"(c[2]), "+f"(c[3])
        : "r"(a[0]), "r"(a[1]), "r"(a[2]), "r"(a[3]), "r"(b0), "r"(b1));
}
// ldmatrix x4: fills 4 fragment regs from 4 8x8 b16 tiles (lane-group addressed)
static __device__ __forceinline__ void ldsm4(uint32_t* r, uint32_t addr) {
    asm volatile("ldmatrix.sync.aligned.m8n8.x4.shared.b16 {%0,%1,%2,%3}, [%4];"
                 : "=r"(r[0]), "=r"(r[1]), "=r"(r[2]), "=r"(r[3]) : "r"(addr));
}

// packed fp32x2 helpers (for the fp32 attention kernels)
__device__ __forceinline__ void ffma2(unsigned long long &d, unsigned long long a,
                                      unsigned long long b) {
    asm("fma.rn.f32x2 %0, %1, %2, %0;" : "+l"(d) : "l"(a), "l"(b));
}
__device__ __forceinline__ unsigned long long dup2(float x) {
    unsigned long long r; unsigned xi = __float_as_uint(x);
    asm("mov.b64 %0, {%1, %1};" : "=l"(r) : "r"(xi));
    return r;
}
__device__ __forceinline__ float lo2(unsigned long long v) {
    return __uint_as_float((unsigned)(v & 0xffffffffull));
}
__device__ __forceinline__ float hi2(unsigned long long v) {
    return __uint_as_float((unsigned)(v >> 32));
}

// ---------------------------------------------------------------------------
// GEMM configuration (256 threads, 8 warps 4Mx2N, warp tile 32x64, single pass)
// ---------------------------------------------------------------------------
#define GBK        32
#define G_NCH      (EMBED / GBK)        /* 32 chunks */
#define PADW       40                   /* fp16 per padded row */
#define ROWB       (PADW * 2)           /* 80 bytes per row */
#define MAT_BYTES  (128 * ROWB)         /* 10240 */
#define STAGE_B    (2 * MAT_BYTES)      /* 20480: A + B only */
#define G_SMEM     (2 * STAGE_B)        /* 40960 */
#define GEMM_BLOCKS (EMBED / 128 * (MTOK / 128))   /* 8 * 256 = 2048 */
#define GRAM_BLOCKS (BHEADS * NCHUNK)              /* 1024 */

static __device__ __forceinline__ void load_chunk(
    uint32_t sb, int buf, int c, int m0, int n0,
    const __half* __restrict__ A, const __half* __restrict__ B, int tid)
{
    const uint32_t st = sb + buf * STAGE_B;
    #pragma unroll
    for (int i = 0; i < 2; i++) {
        const int slot = i * 256 + tid;          // 0..511
        const int row = slot >> 2;               // 0..127
        const int seg = slot & 3;                // 16B segment (8 fp16)
        const uint32_t d = row * ROWB + seg * 16;
        const size_t gA = (size_t)(m0 + row) * EMBED + c * GBK + seg * 8;
        const size_t gB = (size_t)(n0 + row) * EMBED + c * GBK + seg * 8;
        cp16(st + d, A + gA);
        cp16(st + MAT_BYTES + d, B + gB);
    }
    CP_COMMIT();
}

// GEMM body: C = X * W^T + bias (fp16 inputs, fp32 accumulators)
static __device__ __forceinline__ void gemm_body(
    char* smem, int bx,
    const __half* __restrict__ A, const __half* __restrict__ B,
    const float* __restrict__ bias, float* __restrict__ C)
{
    const uint32_t sb = smem_u32(smem);
    const int tid  = threadIdx.x;
    const int wid  = tid >> 5;
    const int lane = tid & 31;
    const int g    = lane >> 2;          // c-fragment row group 0..7
    const int tg   = lane & 3;           // c-fragment col pair 0..3

    const int n0 = (bx & 7) * 128;       // n fastest: CTAs sharing m0 reuse A in L2
    const int m0 = (bx >> 3) * 128;

    const int wm = wid & 3;              // 0..3 -> M offset
    const int wn = wid >> 2;             // 0..1 -> N offset

    const int grp = lane >> 3, lr8 = lane & 7;
    const uint32_t aoff = (uint32_t)((wm * 32 + (grp & 1) * 8 + lr8) * ROWB
                                     + (grp >> 1) * 16);
    const uint32_t boff = (uint32_t)((wn * 64 + (grp >> 1) * 8 + lr8) * ROWB
                                     + (grp & 1) * 16);

    float acc[2][8][4];
    #pragma unroll
    for (int mt = 0; mt < 2; mt++)
        #pragma unroll
        for (int nt = 0; nt < 8; nt++)
            #pragma unroll
            for (int r = 0; r < 4; r++) acc[mt][nt][r] = 0.f;

    load_chunk(sb, 0, 0, m0, n0, A, B, tid);

    for (int c = 0; c < G_NCH; c++) {
        const int buf = c & 1;
        if (c + 1 < G_NCH) {
            load_chunk(sb, buf ^ 1, c + 1, m0, n0, A, B, tid);
            CP_WAIT(1);
        } else {
            CP_WAIT(0);
        }
        __syncthreads();

        const uint32_t stA = sb + buf * STAGE_B;
        const uint32_t stB = stA + MAT_BYTES;

        #pragma unroll
        for (int step = 0; step < 2; step++) {
            const uint32_t so = step * 32;       // 16 fp16 = 32 B along k

            uint32_t a4[2][4];
            #pragma unroll
            for (int mt = 0; mt < 2; mt++)
                ldsm4(a4[mt], stA + aoff + mt * (16 * ROWB) + so);

            #pragma unroll
            for (int pr = 0; pr < 4; pr++) {     // n-row pairs: 2 n8 tiles each
                uint32_t b4[4];
                ldsm4(b4, stB + boff + pr * (16 * ROWB) + so);
                hmma(acc[0][2 * pr],     a4[0], b4[0], b4[1]);
                hmma(acc[0][2 * pr + 1], a4[0], b4[2], b4[3]);
                hmma(acc[1][2 * pr],     a4[1], b4[0], b4[1]);
                hmma(acc[1][2 * pr + 1], a4[1], b4[2], b4[3]);
            }
        }
        __syncthreads();
    }

    #pragma unroll
    for (int mt = 0; mt < 2; mt++) {
        const int row = m0 + wm * 32 + mt * 16 + g;
        #pragma unroll
        for (int nt = 0; nt < 8; nt++) {
            const int col = n0 + wn * 64 + nt * 8 + 2 * tg;
            const float2 bv = *(const float2*)&bias[col];
            float2 v0 = make_float2(acc[mt][nt][0] + bv.x, acc[mt][nt][1] + bv.y);
            float2 v1 = make_float2(acc[mt][nt][2] + bv.x, acc[mt][nt][3] + bv.y);
            *(float2*)&C[(size_t)row * EMBED + col]       = v0;
            *(float2*)&C[(size_t)(row + 8) * EMBED + col] = v1;
        }
    }
}

// Gram body (256 threads): Gpart[c][bh][d][e] = sum_{s in chunk} Q.K (f32x2)
static __device__ __forceinline__ void gram_body(char* smem, int bh, int chunk)
{
    float (*Qs)[64] = (float(*)[64])smem;
    float (*Ks)[64] = (float(*)[64])(smem + 64 * 64 * 4);

    const int b = bh >> 4, h = bh & 15;
    const float* Q = g_QKV[0];
    const float* K = g_QKV[1];
    const size_t base = ((size_t)b * SEQ + (size_t)chunk * SCHUNK) * EMBED + h * DK;

    const int tid = threadIdx.x;
    const int tx = tid & 15, ty = tid >> 4;
    const int lr = tid >> 4, lc4 = (tid & 15) << 2;

    unsigned long long c2[4][2];
    #pragma unroll
    for (int i = 0; i < 4; i++) { c2[i][0] = 0ull; c2[i][1] = 0ull; }

    for (int st = 0; st < SCHUNK / 64; st++) {
        #pragma unroll
        for (int rr = 0; rr < 64; rr += 16) {
            const int s = rr + lr;
            const size_t gg = base + (size_t)(st * 64 + s) * EMBED + lc4;
            *(float4*)&Qs[s][lc4] = *(const float4*)(Q + gg);
            *(float4*)&Ks[s][lc4] = *(const float4*)(K + gg);
        }
        __syncthreads();

        #pragma unroll 8
        for (int ss = 0; ss < 64; ss++) {
            float4 q4 = *(const float4*)&Qs[ss][ty * 4];
            ulonglong2 k2 = *(const ulonglong2*)&Ks[ss][tx * 4];
            float qv[4] = {q4.x, q4.y, q4.z, q4.w};
            #pragma unroll
            for (int i = 0; i < 4; i++) {
                unsigned long long ad = dup2(qv[i]);
                ffma2(c2[i][0], ad, k2.x);
                ffma2(c2[i][1], ad, k2.y);
            }
        }
        __syncthreads();
    }

    float* gp = g_Gpart + ((size_t)chunk * BHEADS + bh) * DK * DK;
    #pragma unroll
    for (int i = 0; i < 4; i++) {
        const int d = ty * 4 + i;
        *(float4*)&gp[d * DK + tx * 4] =
            make_float4(lo2(c2[i][0]), hi2(c2[i][0]), lo2(c2[i][1]), hi2(c2[i][1]));
    }
}

// ---------------------------------------------------------------------------
// Kernel A: fused prep — x fp16 convert + 3x W fp16 convert, one launch.
// ---------------------------------------------------------------------------
#define XB  ((MTOK * EMBED) / 1024)     /* 32768 blocks */
#define WB  ((EMBED * EMBED) / 1024)    /* 1024 blocks per W */

__global__ __launch_bounds__(256)
void prep_kernel(const float* __restrict__ x,
                 const float* __restrict__ Wq, const float* __restrict__ Wk,
                 const float* __restrict__ Wv,
                 __half* __restrict__ xh,
                 __half* __restrict__ w0, __half* __restrict__ w1,
                 __half* __restrict__ w2)
{
    const int bx = blockIdx.x;
    const float* src;
    __half* dst;
    int i;
    if (bx < XB) {
        src = x; dst = xh;
        i = (bx * 256 + threadIdx.x) * 4;
    } else {
        const int wi = (bx - XB) / WB;             // 0..2
        const int wb = (bx - XB) - wi * WB;
        src = (wi == 0) ? Wq : (wi == 1) ? Wk : Wv;
        dst = (wi == 0) ? w0 : (wi == 1) ? w1 : w2;
        i = (wb * 256 + threadIdx.x) * 4;
    }
    float4 v = *(const float4*)(src + i);
    __half2 p0 = {__float2half_rn(v.x), __float2half_rn(v.y)};
    __half2 p1 = {__float2half_rn(v.z), __float2half_rn(v.w)};
    *(__half2*)(dst + i)     = p0;
    *(__half2*)(dst + i + 2) = p1;
}

// ---------------------------------------------------------------------------
// Kernel B: fused Q+K projection GEMM (both single-pass fp16), 4096 blocks
// ---------------------------------------------------------------------------
__global__ __launch_bounds__(256, 2)
void qk_gemm_kernel(const __half* __restrict__ A,
                    const __half* __restrict__ Wq, const __half* __restrict__ Wk,
                    const float* __restrict__ bq, const float* __restrict__ bk,
                    float* __restrict__ Q, float* __restrict__ K)
{
    extern __shared__ char smem[];
    const int bx = blockIdx.x;
    if (bx < GEMM_BLOCKS)
        gemm_body(smem, bx, A, Wq, bq, Q);
    else
        gemm_body(smem, bx - GEMM_BLOCKS, A, Wk, bk, K);
}

// ---------------------------------------------------------------------------
// Kernel C: FUSED V-projection GEMM (single-pass fp16) + gram, interleaved 2:1
// ---------------------------------------------------------------------------
__global__ __launch_bounds__(256, 2)
void vgemm_gram_kernel(const __half* __restrict__ A,
                       const __half* __restrict__ B,
                       const float* __restrict__ bias,
                       float* __restrict__ C)
{
    extern __shared__ char smem[];
    const int bx = blockIdx.x;
    const int r = bx % 3;
    if (r < 2) {
        const int gemm_id = (bx / 3) * 2 + r;        // 0..2047
        gemm_body(smem, gemm_id, A, B, bias, C);
    } else {
        const int gram_id = bx / 3;                  // 0..1023
        gram_body(smem, gram_id & (BHEADS - 1), gram_id >> 7);
    }
}

// ---------------------------------------------------------------------------
// Kernel D: reduce partials + softmax; write attn transposed At[e][d]
// ---------------------------------------------------------------------------
__global__ __launch_bounds__(256)
void softmax_kernel()
{
    const int gwarp = (blockIdx.x * blockDim.x + threadIdx.x) >> 5;
    const int lane = threadIdx.x & 31;
    const int bh = gwarp >> 6;
    const int d = gwarp & 63;

    float g0 = 0.f, g1 = 0.f;
    #pragma unroll
    for (int c = 0; c < NCHUNK; c++) {
        const float* gp = g_Gpart + (((size_t)c * BHEADS + bh) * DK + d) * DK;
        g0 += gp[lane];
        g1 += gp[lane + 32];
    }
    g0 *= 0.125f; g1 *= 0.125f;

    float m = fmaxf(g0, g1);
    #pragma unroll
    for (int o = 16; o > 0; o >>= 1) m = fmaxf(m, __shfl_xor_sync(0xffffffffu, m, o));
    float e0 = expf(g0 - m), e1 = expf(g1 - m);
    float s = e0 + e1;
    #pragma unroll
    for (int o = 16; o > 0; o >>= 1) s += __shfl_xor_sync(0xffffffffu, s, o);
    const float inv = 1.0f / s;

    float* at = g_At + (size_t)bh * DK * DK;
    at[lane * DK + d]        = e0 * inv;
    at[(lane + 32) * DK + d] = e1 * inv;
}

// ---------------------------------------------------------------------------
// Kernel E: output mix  out[m, h*64+d] = sum_e attn[bh][d][e] * V[m, h*64+e]
// ---------------------------------------------------------------------------
__global__ __launch_bounds__(256, 2)
void out_kernel(float* __restrict__ OUT)
{
    __shared__ float Am[64][64];
    __shared__ float Vt[64][65];

    const int m0 = blockIdx.x * 64;
    const int h  = blockIdx.y;
    const int b  = m0 >> 12;
    const int bh = b * NHEADS + h;
    const float* V = g_QKV[2];

    const int tid = threadIdx.x;
    const int tx = tid & 15, ty = tid >> 4;
    const int lr = tid >> 4, lc4 = (tid & 15) << 2;

    const float* at = g_At + (size_t)bh * DK * DK;
    #pragma unroll
    for (int rr = 0; rr < 64; rr += 16)
        *(float4*)&Am[rr + lr][lc4] = *(const float4*)&at[(rr + lr) * DK + lc4];

    #pragma unroll
    for (int rr = 0; rr < 64; rr += 16) {
        const int s = rr + lr;
        float4 v = *(const float4*)(V + (size_t)(m0 + s) * EMBED + h * DK + lc4);
        Vt[lc4 + 0][s] = v.x;
        Vt[lc4 + 1][s] = v.y;
        Vt[lc4 + 2][s] = v.z;
        Vt[lc4 + 3][s] = v.w;
    }
    __syncthreads();

    unsigned long long o2[4][2];
    #pragma unroll
    for (int i = 0; i < 4; i++) { o2[i][0] = 0ull; o2[i][1] = 0ull; }

    #pragma unroll 8
    for (int ee = 0; ee < 64; ee++) {
        ulonglong2 ap = *(const ulonglong2*)&Am[ee][tx * 4];
        #pragma unroll
        for (int si = 0; si < 4; si++) {
            unsigned long long vd = dup2(Vt[ee][ty * 4 + si]);
            ffma2(o2[si][0], vd, ap.x);
            ffma2(o2[si][1], vd, ap.y);
        }
    }

    #pragma unroll
    for (int si = 0; si < 4; si++) {
        const int m = m0 + ty * 4 + si;
        *(float4*)&OUT[(size_t)m * EMBED + h * DK + tx * 4] =
            make_float4(lo2(o2[si][0]), hi2(o2[si][0]),
                        lo2(o2[si][1]), hi2(o2[si][1]));
    }
}

// ---------------------------------------------------------------------------
// Launch
// ---------------------------------------------------------------------------
extern "C" void kernel_launch(void* const* d_in, const int* in_sizes, int n_in,
                              void* d_out, int out_size)
{
    const float* x  = (const float*)d_in[0];
    const float* Wq = (const float*)d_in[1];
    const float* bq = (const float*)d_in[2];
    const float* Wk = (const float*)d_in[3];
    const float* bk = (const float*)d_in[4];
    const float* Wv = (const float*)d_in[5];
    const float* bv = (const float*)d_in[6];
    float* out = (float*)d_out;

    cudaFuncSetAttribute(qk_gemm_kernel,
                         cudaFuncAttributeMaxDynamicSharedMemorySize, G_SMEM);
    cudaFuncSetAttribute(vgemm_gram_kernel,
                         cudaFuncAttributeMaxDynamicSharedMemorySize, G_SMEM);

    __half *xh, *wb;
    cudaGetSymbolAddress((void**)&xh, g_xh);
    cudaGetSymbolAddress((void**)&wb, g_w);
    float* qkv;
    cudaGetSymbolAddress((void**)&qkv, g_QKV);

    __half* w0 = wb;
    __half* w1 = wb + EMBED * EMBED;
    __half* w2 = wb + 2 * EMBED * EMBED;

    // 1) fused conversions (x and all W -> fp16)
    prep_kernel<<<XB + 3 * WB, 256>>>(x, Wq, Wk, Wv, xh, w0, w1, w2);

    // 2) Q and K projections in one launch (single-pass fp16)
    qk_gemm_kernel<<<2 * GEMM_BLOCKS, 256, G_SMEM>>>(
        xh, w0, w1, bq, bk,
        qkv + 0ll * MTOK * EMBED, qkv + 1ll * MTOK * EMBED);

    // 3) fused: V projection (tensor pipe) + gram over Q,K (fma pipe)
    vgemm_gram_kernel<<<GEMM_BLOCKS + GRAM_BLOCKS, 256, G_SMEM>>>(
        xh, w2, bv, qkv + 2ll * MTOK * EMBED);

    // 4) softmax + output mix
    softmax_kernel<<<(BHEADS * DK) / 8, 256>>>();
    out_kernel<<<dim3(MTOK / 64, NHEADS), 256>>>(out);
}

// round 16
// speedup vs baseline: 1.7153x; 1.0779x over previous
#include <cuda_runtime.h>
#include <cuda_bf16.h>
#include <cuda_fp16.h>
#include <cstdint>

#define EMBED   1024
#define NHEADS  16
#define DK      64
#define BATCH   8
#define SEQ     4096
#define MTOK    (BATCH * SEQ)      /* 32768 tokens */
#define BHEADS  (BATCH * NHEADS)   /* 128 head-instances */
#define NCHUNK  8
#define SCHUNK  (SEQ / NCHUNK)     /* 512 */

// ---------------------------------------------------------------------------
// Scratch (__device__ globals: the sanctioned no-alloc workaround)
// ---------------------------------------------------------------------------
__device__ float  g_QK[2][MTOK * EMBED];                     // fp32 Q, K
__device__ __half g_Vh[MTOK * EMBED];                        // fp16 V
__device__ float  g_Gpart[NCHUNK * BHEADS * DK * DK];        // gram partials
__device__ __half g_Ath[BHEADS * DK * DK];                   // fp16 attn [d][e]
__device__ __half g_xh[MTOK * EMBED];                        // x fp16
__device__ __half g_w[3][EMBED * EMBED];                     // W fp16 (q,k,v)

// ---------------------------------------------------------------------------
// helpers
// ---------------------------------------------------------------------------
static __device__ __forceinline__ uint32_t smem_u32(const void* p) {
    uint32_t a;
    asm("{ .reg .u64 t; cvta.to.shared.u64 t, %1; cvt.u32.u64 %0, t; }"
        : "=r"(a) : "l"(p));
    return a;
}
static __device__ __forceinline__ void cp16(uint32_t dst, const void* src) {
    asm volatile("cp.async.cg.shared.global [%0], [%1], 16;" :: "r"(dst), "l"(src));
}
#define CP_COMMIT()  asm volatile("cp.async.commit_group;" ::: "memory")
#define CP_WAIT(n)   asm volatile("cp.async.wait_group %0;" :: "n"(n) : "memory")

// mma.sync m16n8k16 row.col f32.f16.f16.f32 (baseline sm_80+ path)
static __device__ __forceinline__ void hmma(float* c, const uint32_t* a,
                                            uint32_t b0, uint32_t b1) {
    asm volatile(
        "mma.sync.aligned.m16n8k16.row.col.f32.f16.f16.f32 "
        "{%0,%1,%2,%3}, {%4,%5,%6,%7}, {%8,%9}, {%0,%1,%2,%3};"
        : "+f"(c[0]), "+f"(c[1]), "+f"(c[2]), "+f"(c[3])
        : "r"(a[0]), "r"(a[1]), "r"(a[2]), "r"(a[3]), "r"(b0), "r"(b1));
}
// ldmatrix x4: fills 4 fragment regs from 4 8x8 b16 tiles (lane-group addressed)
static __device__ __forceinline__ void ldsm4(uint32_t* r, uint32_t addr) {
    asm volatile("ldmatrix.sync.aligned.m8n8.x4.shared.b16 {%0,%1,%2,%3}, [%4];"
                 : "=r"(r[0]), "=r"(r[1]), "=r"(r[2]), "=r"(r[3]) : "r"(addr));
}

// packed fp32x2 helpers (for the fp32 gram kernel)
__device__ __forceinline__ void ffma2(unsigned long long &d, unsigned long long a,
                                      unsigned long long b) {
    asm("fma.rn.f32x2 %0, %1, %2, %0;" : "+l"(d) : "l"(a), "l"(b));
}
__device__ __forceinline__ unsigned long long dup2(float x) {
    unsigned long long r; unsigned xi = __float_as_uint(x);
    asm("mov.b64 %0, {%1, %1};" : "=l"(r) : "r"(xi));
    return r;
}
__device__ __forceinline__ float lo2(unsigned long long v) {
    return __uint_as_float((unsigned)(v & 0xffffffffull));
}
__device__ __forceinline__ float hi2(unsigned long long v) {
    return __uint_as_float((unsigned)(v >> 32));
}

// ---------------------------------------------------------------------------
// GEMM configuration (256 threads, 8 warps 4Mx2N, warp tile 32x64, single pass)
// ---------------------------------------------------------------------------
#define GBK        32
#define G_NCH      (EMBED / GBK)        /* 32 chunks */
#define PADW       40                   /* fp16 per padded row */
#define ROWB       (PADW * 2)           /* 80 bytes per row */
#define MAT_BYTES  (128 * ROWB)         /* 10240 */
#define STAGE_B    (2 * MAT_BYTES)      /* 20480: A + B */
#define G_SMEM     (2 * STAGE_B)        /* 40960 */
#define GEMM_BLOCKS (EMBED / 128 * (MTOK / 128))   /* 2048 */
#define GRAM_BLOCKS (BHEADS * NCHUNK)              /* 1024 */

static __device__ __forceinline__ void load_chunk(
    uint32_t sb, int buf, int c, int m0, int n0,
    const __half* __restrict__ A, const __half* __restrict__ B, int tid)
{
    const uint32_t st = sb + buf * STAGE_B;
    #pragma unroll
    for (int i = 0; i < 2; i++) {
        const int slot = i * 256 + tid;          // 0..511
        const int row = slot >> 2;               // 0..127
        const int seg = slot & 3;                // 16B segment (8 fp16)
        const uint32_t d = row * ROWB + seg * 16;
        const size_t gA = (size_t)(m0 + row) * EMBED + c * GBK + seg * 8;
        const size_t gB = (size_t)(n0 + row) * EMBED + c * GBK + seg * 8;
        cp16(st + d, A + gA);
        cp16(st + MAT_BYTES + d, B + gB);
    }
    CP_COMMIT();
}

// GEMM body: C = X * W^T + bias (fp16 inputs, fp32 accumulators)
// HALF_OUT: write fp16 output (for V); else fp32.
template <bool HALF_OUT>
static __device__ __forceinline__ void gemm_body(
    char* smem, int bx,
    const __half* __restrict__ A, const __half* __restrict__ B,
    const float* __restrict__ bias, void* __restrict__ Cv)
{
    const uint32_t sb = smem_u32(smem);
    const int tid  = threadIdx.x;
    const int wid  = tid >> 5;
    const int lane = tid & 31;
    const int g    = lane >> 2;          // c-fragment row group 0..7
    const int tg   = lane & 3;           // c-fragment col pair 0..3

    const int n0 = (bx & 7) * 128;       // n fastest: CTAs sharing m0 reuse A in L2
    const int m0 = (bx >> 3) * 128;

    const int wm = wid & 3;              // 0..3 -> M offset
    const int wn = wid >> 2;             // 0..1 -> N offset

    const int grp = lane >> 3, lr8 = lane & 7;
    const uint32_t aoff = (uint32_t)((wm * 32 + (grp & 1) * 8 + lr8) * ROWB
                                     + (grp >> 1) * 16);
    const uint32_t boff = (uint32_t)((wn * 64 + (grp >> 1) * 8 + lr8) * ROWB
                                     + (grp & 1) * 16);

    float acc[2][8][4];
    #pragma unroll
    for (int mt = 0; mt < 2; mt++)
        #pragma unroll
        for (int nt = 0; nt < 8; nt++)
            #pragma unroll
            for (int r = 0; r < 4; r++) acc[mt][nt][r] = 0.f;

    load_chunk(sb, 0, 0, m0, n0, A, B, tid);

    for (int c = 0; c < G_NCH; c++) {
        const int buf = c & 1;
        if (c + 1 < G_NCH) {
            load_chunk(sb, buf ^ 1, c + 1, m0, n0, A, B, tid);
            CP_WAIT(1);
        } else {
            CP_WAIT(0);
        }
        __syncthreads();

        const uint32_t stA = sb + buf * STAGE_B;
        const uint32_t stB = stA + MAT_BYTES;

        #pragma unroll
        for (int step = 0; step < 2; step++) {
            const uint32_t so = step * 32;       // 16 fp16 = 32 B along k

            uint32_t a4[2][4];
            #pragma unroll
            for (int mt = 0; mt < 2; mt++)
                ldsm4(a4[mt], stA + aoff + mt * (16 * ROWB) + so);

            #pragma unroll
            for (int pr = 0; pr < 4; pr++) {     // n-row pairs: 2 n8 tiles each
                uint32_t b4[4];
                ldsm4(b4, stB + boff + pr * (16 * ROWB) + so);
                hmma(acc[0][2 * pr],     a4[0], b4[0], b4[1]);
                hmma(acc[0][2 * pr + 1], a4[0], b4[2], b4[3]);
                hmma(acc[1][2 * pr],     a4[1], b4[0], b4[1]);
                hmma(acc[1][2 * pr + 1], a4[1], b4[2], b4[3]);
            }
        }
        __syncthreads();
    }

    #pragma unroll
    for (int mt = 0; mt < 2; mt++) {
        const int row = m0 + wm * 32 + mt * 16 + g;
        #pragma unroll
        for (int nt = 0; nt < 8; nt++) {
            const int col = n0 + wn * 64 + nt * 8 + 2 * tg;
            const float2 bv = *(const float2*)&bias[col];
            const float c00 = acc[mt][nt][0] + bv.x;
            const float c01 = acc[mt][nt][1] + bv.y;
            const float c10 = acc[mt][nt][2] + bv.x;
            const float c11 = acc[mt][nt][3] + bv.y;
            if (HALF_OUT) {
                __half* C = (__half*)Cv;
                __half2 h0 = {__float2half_rn(c00), __float2half_rn(c01)};
                __half2 h1 = {__float2half_rn(c10), __float2half_rn(c11)};
                *(__half2*)&C[(size_t)row * EMBED + col]       = h0;
                *(__half2*)&C[(size_t)(row + 8) * EMBED + col] = h1;
            } else {
                float* C = (float*)Cv;
                *(float2*)&C[(size_t)row * EMBED + col]       = make_float2(c00, c01);
                *(float2*)&C[(size_t)(row + 8) * EMBED + col] = make_float2(c10, c11);
            }
        }
    }
}

// ---------------------------------------------------------------------------
// Kernel A: fused prep — x fp16 convert + 3x W fp16 convert, one launch.
// ---------------------------------------------------------------------------
#define XB  ((MTOK * EMBED) / 1024)     /* 32768 blocks */
#define WB  ((EMBED * EMBED) / 1024)    /* 1024 blocks per W */

__global__ __launch_bounds__(256)
void prep_kernel(const float* __restrict__ x,
                 const float* __restrict__ Wq, const float* __restrict__ Wk,
                 const float* __restrict__ Wv,
                 __half* __restrict__ xh,
                 __half* __restrict__ w0, __half* __restrict__ w1,
                 __half* __restrict__ w2)
{
    const int bx = blockIdx.x;
    const float* src;
    __half* dst;
    int i;
    if (bx < XB) {
        src = x; dst = xh;
        i = (bx * 256 + threadIdx.x) * 4;
    } else {
        const int wi = (bx - XB) / WB;             // 0..2
        const int wb = (bx - XB) - wi * WB;
        src = (wi == 0) ? Wq : (wi == 1) ? Wk : Wv;
        dst = (wi == 0) ? w0 : (wi == 1) ? w1 : w2;
        i = (wb * 256 + threadIdx.x) * 4;
    }
    float4 v = *(const float4*)(src + i);
    __half2 p0 = {__float2half_rn(v.x), __float2half_rn(v.y)};
    __half2 p1 = {__float2half_rn(v.z), __float2half_rn(v.w)};
    *(__half2*)(dst + i)     = p0;
    *(__half2*)(dst + i + 2) = p1;
}

// ---------------------------------------------------------------------------
// Kernel B: fused Q+K projection GEMM (fp32 outputs), 4096 blocks
// ---------------------------------------------------------------------------
__global__ __launch_bounds__(256, 2)
void qk_gemm_kernel(const __half* __restrict__ A,
                    const __half* __restrict__ Wq, const __half* __restrict__ Wk,
                    const float* __restrict__ bq, const float* __restrict__ bk,
                    float* __restrict__ Q, float* __restrict__ K)
{
    extern __shared__ char smem[];
    const int bx = blockIdx.x;
    if (bx < GEMM_BLOCKS)
        gemm_body<false>(smem, bx, A, Wq, bq, Q);
    else
        gemm_body<false>(smem, bx - GEMM_BLOCKS, A, Wk, bk, K);
}

// ---------------------------------------------------------------------------
// Kernel C: V projection GEMM, fp16 output
// ---------------------------------------------------------------------------
__global__ __launch_bounds__(256, 2)
void v_gemm_kernel(const __half* __restrict__ A, const __half* __restrict__ B,
                   const float* __restrict__ bias, __half* __restrict__ C)
{
    extern __shared__ char smem[];
    gemm_body<true>(smem, blockIdx.x, A, B, bias, C);
}

// ---------------------------------------------------------------------------
// Kernel D: Gram partials (fp32, f32x2). Gpart[c][bh][d][e] = sum_s Q.K
// ---------------------------------------------------------------------------
__global__ __launch_bounds__(256, 2)
void gram_kernel()
{
    __shared__ float Qs[64][64];
    __shared__ float Ks[64][64];

    const int bh = blockIdx.x & (BHEADS - 1);
    const int chunk = blockIdx.x >> 7;
    const int b = bh >> 4, h = bh & 15;
    const float* Q = g_QK[0];
    const float* K = g_QK[1];
    const size_t base = ((size_t)b * SEQ + (size_t)chunk * SCHUNK) * EMBED + h * DK;

    const int tid = threadIdx.x;
    const int tx = tid & 15, ty = tid >> 4;
    const int lr = tid >> 4, lc4 = (tid & 15) << 2;

    unsigned long long c2[4][2];
    #pragma unroll
    for (int i = 0; i < 4; i++) { c2[i][0] = 0ull; c2[i][1] = 0ull; }

    for (int st = 0; st < SCHUNK / 64; st++) {
        #pragma unroll
        for (int rr = 0; rr < 64; rr += 16) {
            const int s = rr + lr;
            const size_t gg = base + (size_t)(st * 64 + s) * EMBED + lc4;
            *(float4*)&Qs[s][lc4] = *(const float4*)(Q + gg);
            *(float4*)&Ks[s][lc4] = *(const float4*)(K + gg);
        }
        __syncthreads();

        #pragma unroll 8
        for (int ss = 0; ss < 64; ss++) {
            float4 q4 = *(const float4*)&Qs[ss][ty * 4];
            ulonglong2 k2 = *(const ulonglong2*)&Ks[ss][tx * 4];
            float qv[4] = {q4.x, q4.y, q4.z, q4.w};
            #pragma unroll
            for (int i = 0; i < 4; i++) {
                unsigned long long ad = dup2(qv[i]);
                ffma2(c2[i][0], ad, k2.x);
                ffma2(c2[i][1], ad, k2.y);
            }
        }
        __syncthreads();
    }

    float* gp = g_Gpart + ((size_t)chunk * BHEADS + bh) * DK * DK;
    #pragma unroll
    for (int i = 0; i < 4; i++) {
        const int d = ty * 4 + i;
        *(float4*)&gp[d * DK + tx * 4] =
            make_float4(lo2(c2[i][0]), hi2(c2[i][0]), lo2(c2[i][1]), hi2(c2[i][1]));
    }
}

// ---------------------------------------------------------------------------
// Kernel E: reduce partials + softmax; write fp16 attn [d][e] row-major
// ---------------------------------------------------------------------------
__global__ __launch_bounds__(256)
void softmax_kernel()
{
    const int gwarp = (blockIdx.x * blockDim.x + threadIdx.x) >> 5;
    const int lane = threadIdx.x & 31;
    const int bh = gwarp >> 6;
    const int d = gwarp & 63;

    float g0 = 0.f, g1 = 0.f;
    #pragma unroll
    for (int c = 0; c < NCHUNK; c++) {
        const float* gp = g_Gpart + (((size_t)c * BHEADS + bh) * DK + d) * DK;
        g0 += gp[lane];
        g1 += gp[lane + 32];
    }
    g0 *= 0.125f; g1 *= 0.125f;

    float m = fmaxf(g0, g1);
    #pragma unroll
    for (int o = 16; o > 0; o >>= 1) m = fmaxf(m, __shfl_xor_sync(0xffffffffu, m, o));
    float e0 = expf(g0 - m), e1 = expf(g1 - m);
    float s = e0 + e1;
    #pragma unroll
    for (int o = 16; o > 0; o >>= 1) s += __shfl_xor_sync(0xffffffffu, s, o);
    const float inv = 1.0f / s;

    __half* at = g_Ath + (size_t)bh * DK * DK;
    at[d * DK + lane]      = __float2half_rn(e0 * inv);
    at[d * DK + lane + 32] = __float2half_rn(e1 * inv);
}

// ---------------------------------------------------------------------------
// Kernel F: HMMA output mix.
//   out[m][h*64+d] = sum_e attn[bh][d][e] * V[m][h*64+e]
// mma mapping: m=token, n=d, k=e. A = V tile [128 x 64], B = attn [64 x 64]
// (both k-contiguous, exactly the projection-GEMM operand layout).
// 256 threads, 8 warps, warp = m16 x n64: 4 k-steps x (1 A-ldsm4 + 4 B-ldsm4,
// 8 HMMA). Padded rows: 72 fp16 = 144 B (8-row ldmatrix phase conflict-free).
// ---------------------------------------------------------------------------
#define PADO 72
#define OROW (PADO * 2)     /* 144 bytes */

__global__ __launch_bounds__(256, 2)
void out_hmma_kernel(const __half* __restrict__ Vh, float* __restrict__ OUT)
{
    __shared__ __align__(16) char sm[128 * OROW + 64 * OROW];

    const int m0 = blockIdx.x * 128;
    const int h  = blockIdx.y;
    const int b  = m0 >> 12;
    const int bh = b * NHEADS + h;

    const int tid = threadIdx.x;
    const int wid = tid >> 5;
    const int lane = tid & 31;
    const int g = lane >> 2, tg = lane & 3;
    const int grp = lane >> 3, lr8 = lane & 7;

    // load V tile [128 x 64] fp16 -> smem rows of 144 B
    #pragma unroll
    for (int i = 0; i < 4; i++) {
        const int slot = i * 256 + tid;          // 0..1023
        const int row = slot >> 3, seg = slot & 7;
        *(uint4*)(sm + row * OROW + seg * 16) =
            *(const uint4*)(Vh + (size_t)(m0 + row) * EMBED + h * 64 + seg * 8);
    }
    // load attn [64 x 64] fp16
    const __half* at = g_Ath + (size_t)bh * DK * DK;
    #pragma unroll
    for (int i = 0; i < 2; i++) {
        const int slot = i * 256 + tid;          // 0..511
        const int row = slot >> 3, seg = slot & 7;
        *(uint4*)(sm + 128 * OROW + row * OROW + seg * 16) =
            *(const uint4*)(at + row * 64 + seg * 8);
    }
    __syncthreads();

    const uint32_t sb = smem_u32(sm);
    const uint32_t aoff = sb + (uint32_t)((wid * 16 + (grp & 1) * 8 + lr8) * OROW
                                          + (grp >> 1) * 16);
    const uint32_t boff = sb + 128 * OROW
                        + (uint32_t)(((grp >> 1) * 8 + lr8) * OROW + (grp & 1) * 16);

    float acc[8][4];
    #pragma unroll
    for (int nt = 0; nt < 8; nt++)
        #pragma unroll
        for (int r = 0; r < 4; r++) acc[nt][r] = 0.f;

    #pragma unroll
    for (int ks = 0; ks < 4; ks++) {
        const uint32_t so = ks * 32;             // 16 fp16 along e
        uint32_t a4[4];
        ldsm4(a4, aoff + so);
        #pragma unroll
        for (int pr = 0; pr < 4; pr++) {
            uint32_t b4[4];
            ldsm4(b4, boff + pr * (16 * OROW) + so);
            hmma(acc[2 * pr],     a4, b4[0], b4[1]);
            hmma(acc[2 * pr + 1], a4, b4[2], b4[3]);
        }
    }

    const int row = m0 + wid * 16 + g;
    #pragma unroll
    for (int nt = 0; nt < 8; nt++) {
        const int col = h * 64 + nt * 8 + 2 * tg;
        *(float2*)&OUT[(size_t)row * EMBED + col] =
            make_float2(acc[nt][0], acc[nt][1]);
        *(float2*)&OUT[(size_t)(row + 8) * EMBED + col] =
            make_float2(acc[nt][2], acc[nt][3]);
    }
}

// ---------------------------------------------------------------------------
// Launch
// ---------------------------------------------------------------------------
extern "C" void kernel_launch(void* const* d_in, const int* in_sizes, int n_in,
                              void* d_out, int out_size)
{
    const float* x  = (const float*)d_in[0];
    const float* Wq = (const float*)d_in[1];
    const float* bq = (const float*)d_in[2];
    const float* Wk = (const float*)d_in[3];
    const float* bk = (const float*)d_in[4];
    const float* Wv = (const float*)d_in[5];
    const float* bv = (const float*)d_in[6];
    float* out = (float*)d_out;

    cudaFuncSetAttribute(qk_gemm_kernel,
                         cudaFuncAttributeMaxDynamicSharedMemorySize, G_SMEM);
    cudaFuncSetAttribute(v_gemm_kernel,
                         cudaFuncAttributeMaxDynamicSharedMemorySize, G_SMEM);

    __half *xh, *wb, *vh;
    cudaGetSymbolAddress((void**)&xh, g_xh);
    cudaGetSymbolAddress((void**)&wb, g_w);
    cudaGetSymbolAddress((void**)&vh, g_Vh);
    float* qk;
    cudaGetSymbolAddress((void**)&qk, g_QK);

    __half* w0 = wb;
    __half* w1 = wb + EMBED * EMBED;
    __half* w2 = wb + 2 * EMBED * EMBED;

    // 1) fused conversions (x and all W -> fp16)
    prep_kernel<<<XB + 3 * WB, 256>>>(x, Wq, Wk, Wv, xh, w0, w1, w2);

    // 2) Q and K projections in one launch (fp32 out, feeds fp32 gram)
    qk_gemm_kernel<<<2 * GEMM_BLOCKS, 256, G_SMEM>>>(
        xh, w0, w1, bq, bk, qk, qk + 1ll * MTOK * EMBED);

    // 3) V projection (fp16 out) then gram (serial beats the old fusion)
    v_gemm_kernel<<<GEMM_BLOCKS, 256, G_SMEM>>>(xh, w2, bv, vh);
    gram_kernel<<<GRAM_BLOCKS, 256>>>();

    // 4) softmax (fp16 attn) + HMMA output mix
    softmax_kernel<<<(BHEADS * DK) / 8, 256>>>();
    out_hmma_kernel<<<dim3(MTOK / 128, NHEADS), 256>>>(vh, out);
}

// round 17
// speedup vs baseline: 1.7783x; 1.0367x over previous
#include <cuda_runtime.h>
#include <cuda_bf16.h>
#include <cuda_fp16.h>
#include <cstdint>

#define EMBED   1024
#define NHEADS  16
#define DK      64
#define BATCH   8
#define SEQ     4096
#define MTOK    (BATCH * SEQ)      /* 32768 tokens */
#define BHEADS  (BATCH * NHEADS)   /* 128 head-instances */
#define NCHUNK  8
#define SCHUNK  (SEQ / NCHUNK)     /* 512 */

// ---------------------------------------------------------------------------
// Scratch (__device__ globals: the sanctioned no-alloc workaround)
// ---------------------------------------------------------------------------
__device__ __half g_Qh[MTOK * EMBED];                        // Q fp16 hi
__device__ __half g_Ql[MTOK * EMBED];                        // Q fp16 lo
__device__ __half g_Kh[MTOK * EMBED];                        // K fp16 hi
__device__ __half g_Kl[MTOK * EMBED];                        // K fp16 lo
__device__ __half g_Vh[MTOK * EMBED];                        // fp16 V
__device__ float  g_Gpart[NCHUNK * BHEADS * DK * DK];        // gram partials
__device__ __half g_Ath[BHEADS * DK * DK];                   // fp16 attn [d][e]
__device__ __half g_xh[MTOK * EMBED];                        // x fp16
__device__ __half g_w[3][EMBED * EMBED];                     // W fp16 (q,k,v)

// ---------------------------------------------------------------------------
// helpers
// ---------------------------------------------------------------------------
static __device__ __forceinline__ uint32_t smem_u32(const void* p) {
    uint32_t a;
    asm("{ .reg .u64 t; cvta.to.shared.u64 t, %1; cvt.u32.u64 %0, t; }"
        : "=r"(a) : "l"(p));
    return a;
}
static __device__ __forceinline__ void cp16(uint32_t dst, const void* src) {
    asm volatile("cp.async.cg.shared.global [%0], [%1], 16;" :: "r"(dst), "l"(src));
}
#define CP_COMMIT()  asm volatile("cp.async.commit_group;" ::: "memory")
#define CP_WAIT(n)   asm volatile("cp.async.wait_group %0;" :: "n"(n) : "memory")

// mma.sync m16n8k16 row.col f32.f16.f16.f32 (baseline sm_80+ path)
static __device__ __forceinline__ void hmma(float* c, const uint32_t* a,
                                            uint32_t b0, uint32_t b1) {
    asm volatile(
        "mma.sync.aligned.m16n8k16.row.col.f32.f16.f16.f32 "
        "{%0,%1,%2,%3}, {%4,%5,%6,%7}, {%8,%9}, {%0,%1,%2,%3};"
        : "+f"(c[0]), "+f"(c[1]), "+f"(c[2]), "+f"(c[3])
        : "r"(a[0]), "r"(a[1]), "r"(a[2]), "r"(a[3]), "r"(b0), "r"(b1));
}
// ldmatrix x4 (non-transposing)
static __device__ __forceinline__ void ldsm4(uint32_t* r, uint32_t addr) {
    asm volatile("ldmatrix.sync.aligned.m8n8.x4.shared.b16 {%0,%1,%2,%3}, [%4];"
                 : "=r"(r[0]), "=r"(r[1]), "=r"(r[2]), "=r"(r[3]) : "r"(addr));
}
// ldmatrix x4 transposing: source tiles [k][m] -> fragments [m][k]
static __device__ __forceinline__ void ldsm4t(uint32_t* r, uint32_t addr) {
    asm volatile("ldmatrix.sync.aligned.m8n8.x4.trans.shared.b16 {%0,%1,%2,%3}, [%4];"
                 : "=r"(r[0]), "=r"(r[1]), "=r"(r[2]), "=r"(r[3]) : "r"(addr));
}

// ---------------------------------------------------------------------------
// GEMM configuration (256 threads, 8 warps 4Mx2N, warp tile 32x64, single pass)
// ---------------------------------------------------------------------------
#define GBK        32
#define G_NCH      (EMBED / GBK)        /* 32 chunks */
#define PADW       40                   /* fp16 per padded row */
#define ROWB       (PADW * 2)           /* 80 bytes per row */
#define MAT_BYTES  (128 * ROWB)         /* 10240 */
#define STAGE_B    (2 * MAT_BYTES)      /* 20480: A + B */
#define G_SMEM     (2 * STAGE_B)        /* 40960 */
#define GEMM_BLOCKS (EMBED / 128 * (MTOK / 128))   /* 2048 */
#define GRAM_BLOCKS (BHEADS * NCHUNK)              /* 1024 */

static __device__ __forceinline__ void load_chunk(
    uint32_t sb, int buf, int c, int m0, int n0,
    const __half* __restrict__ A, const __half* __restrict__ B, int tid)
{
    const uint32_t st = sb + buf * STAGE_B;
    #pragma unroll
    for (int i = 0; i < 2; i++) {
        const int slot = i * 256 + tid;          // 0..511
        const int row = slot >> 2;               // 0..127
        const int seg = slot & 3;                // 16B segment (8 fp16)
        const uint32_t d = row * ROWB + seg * 16;
        const size_t gA = (size_t)(m0 + row) * EMBED + c * GBK + seg * 8;
        const size_t gB = (size_t)(n0 + row) * EMBED + c * GBK + seg * 8;
        cp16(st + d, A + gA);
        cp16(st + MAT_BYTES + d, B + gB);
    }
    CP_COMMIT();
}

// GEMM body: C = X * W^T + bias (fp16 inputs, fp32 accumulators)
// MODE 0: write fp16 hi/lo split to C0/C1 (Q,K).  MODE 1: fp16 out to C0 (V).
template <int MODE>
static __device__ __forceinline__ void gemm_body(
    char* smem, int bx,
    const __half* __restrict__ A, const __half* __restrict__ B,
    const float* __restrict__ bias,
    __half* __restrict__ C0, __half* __restrict__ C1)
{
    const uint32_t sb = smem_u32(smem);
    const int tid  = threadIdx.x;
    const int wid  = tid >> 5;
    const int lane = tid & 31;
    const int g    = lane >> 2;          // c-fragment row group 0..7
    const int tg   = lane & 3;           // c-fragment col pair 0..3

    const int n0 = (bx & 7) * 128;       // n fastest: CTAs sharing m0 reuse A in L2
    const int m0 = (bx >> 3) * 128;

    const int wm = wid & 3;              // 0..3 -> M offset
    const int wn = wid >> 2;             // 0..1 -> N offset

    const int grp = lane >> 3, lr8 = lane & 7;
    const uint32_t aoff = (uint32_t)((wm * 32 + (grp & 1) * 8 + lr8) * ROWB
                                     + (grp >> 1) * 16);
    const uint32_t boff = (uint32_t)((wn * 64 + (grp >> 1) * 8 + lr8) * ROWB
                                     + (grp & 1) * 16);

    float acc[2][8][4];
    #pragma unroll
    for (int mt = 0; mt < 2; mt++)
        #pragma unroll
        for (int nt = 0; nt < 8; nt++)
            #pragma unroll
            for (int r = 0; r < 4; r++) acc[mt][nt][r] = 0.f;

    load_chunk(sb, 0, 0, m0, n0, A, B, tid);

    for (int c = 0; c < G_NCH; c++) {
        const int buf = c & 1;
        if (c + 1 < G_NCH) {
            load_chunk(sb, buf ^ 1, c + 1, m0, n0, A, B, tid);
            CP_WAIT(1);
        } else {
            CP_WAIT(0);
        }
        __syncthreads();

        const uint32_t stA = sb + buf * STAGE_B;
        const uint32_t stB = stA + MAT_BYTES;

        #pragma unroll
        for (int step = 0; step < 2; step++) {
            const uint32_t so = step * 32;       // 16 fp16 = 32 B along k

            uint32_t a4[2][4];
            #pragma unroll
            for (int mt = 0; mt < 2; mt++)
                ldsm4(a4[mt], stA + aoff + mt * (16 * ROWB) + so);

            #pragma unroll
            for (int pr = 0; pr < 4; pr++) {     // n-row pairs: 2 n8 tiles each
                uint32_t b4[4];
                ldsm4(b4, stB + boff + pr * (16 * ROWB) + so);
                hmma(acc[0][2 * pr],     a4[0], b4[0], b4[1]);
                hmma(acc[0][2 * pr + 1], a4[0], b4[2], b4[3]);
                hmma(acc[1][2 * pr],     a4[1], b4[0], b4[1]);
                hmma(acc[1][2 * pr + 1], a4[1], b4[2], b4[3]);
            }
        }
        __syncthreads();
    }

    #pragma unroll
    for (int mt = 0; mt < 2; mt++) {
        const int row = m0 + wm * 32 + mt * 16 + g;
        #pragma unroll
        for (int nt = 0; nt < 8; nt++) {
            const int col = n0 + wn * 64 + nt * 8 + 2 * tg;
            const float2 bv = *(const float2*)&bias[col];
            const float c00 = acc[mt][nt][0] + bv.x;
            const float c01 = acc[mt][nt][1] + bv.y;
            const float c10 = acc[mt][nt][2] + bv.x;
            const float c11 = acc[mt][nt][3] + bv.y;
            if (MODE == 1) {
                __half2 h0 = {__float2half_rn(c00), __float2half_rn(c01)};
                __half2 h1 = {__float2half_rn(c10), __float2half_rn(c11)};
                *(__half2*)&C0[(size_t)row * EMBED + col]       = h0;
                *(__half2*)&C0[(size_t)(row + 8) * EMBED + col] = h1;
            } else {
                __half h00 = __float2half_rn(c00), h01 = __float2half_rn(c01);
                __half h10 = __float2half_rn(c10), h11 = __float2half_rn(c11);
                __half2 hh0 = {h00, h01}, hh1 = {h10, h11};
                __half2 ll0 = {__float2half_rn(c00 - __half2float(h00)),
                               __float2half_rn(c01 - __half2float(h01))};
                __half2 ll1 = {__float2half_rn(c10 - __half2float(h10)),
                               __float2half_rn(c11 - __half2float(h11))};
                *(__half2*)&C0[(size_t)row * EMBED + col]       = hh0;
                *(__half2*)&C0[(size_t)(row + 8) * EMBED + col] = hh1;
                *(__half2*)&C1[(size_t)row * EMBED + col]       = ll0;
                *(__half2*)&C1[(size_t)(row + 8) * EMBED + col] = ll1;
            }
        }
    }
}

// ---------------------------------------------------------------------------
// Kernel A: fused prep — x fp16 convert + 3x W fp16 convert, one launch.
// ---------------------------------------------------------------------------
#define XB  ((MTOK * EMBED) / 1024)     /* 32768 blocks */
#define WB  ((EMBED * EMBED) / 1024)    /* 1024 blocks per W */

__global__ __launch_bounds__(256)
void prep_kernel(const float* __restrict__ x,
                 const float* __restrict__ Wq, const float* __restrict__ Wk,
                 const float* __restrict__ Wv,
                 __half* __restrict__ xh,
                 __half* __restrict__ w0, __half* __restrict__ w1,
                 __half* __restrict__ w2)
{
    const int bx = blockIdx.x;
    const float* src;
    __half* dst;
    int i;
    if (bx < XB) {
        src = x; dst = xh;
        i = (bx * 256 + threadIdx.x) * 4;
    } else {
        const int wi = (bx - XB) / WB;             // 0..2
        const int wb = (bx - XB) - wi * WB;
        src = (wi == 0) ? Wq : (wi == 1) ? Wk : Wv;
        dst = (wi == 0) ? w0 : (wi == 1) ? w1 : w2;
        i = (wb * 256 + threadIdx.x) * 4;
    }
    float4 v = *(const float4*)(src + i);
    __half2 p0 = {__float2half_rn(v.x), __float2half_rn(v.y)};
    __half2 p1 = {__float2half_rn(v.z), __float2half_rn(v.w)};
    *(__half2*)(dst + i)     = p0;
    *(__half2*)(dst + i + 2) = p1;
}

// ---------------------------------------------------------------------------
// Kernel B: fused Q+K projection GEMM (fp16 hi/lo outputs), 4096 blocks
// ---------------------------------------------------------------------------
__global__ __launch_bounds__(256, 2)
void qk_gemm_kernel(const __half* __restrict__ A,
                    const __half* __restrict__ Wq, const __half* __restrict__ Wk,
                    const float* __restrict__ bq, const float* __restrict__ bk,
                    __half* __restrict__ Qh, __half* __restrict__ Ql,
                    __half* __restrict__ Kh, __half* __restrict__ Kl)
{
    extern __shared__ char smem[];
    const int bx = blockIdx.x;
    if (bx < GEMM_BLOCKS)
        gemm_body<0>(smem, bx, A, Wq, bq, Qh, Ql);
    else
        gemm_body<0>(smem, bx - GEMM_BLOCKS, A, Wk, bk, Kh, Kl);
}

// ---------------------------------------------------------------------------
// Kernel C: V projection GEMM, fp16 output
// ---------------------------------------------------------------------------
__global__ __launch_bounds__(256, 2)
void v_gemm_kernel(const __half* __restrict__ A, const __half* __restrict__ B,
                   const float* __restrict__ bias, __half* __restrict__ C)
{
    extern __shared__ char smem[];
    gemm_body<1>(smem, blockIdx.x, A, B, bias, C, nullptr);
}

// ---------------------------------------------------------------------------
// Kernel D: HMMA gram.  Gpart[c][bh][d][e] = sum_{s in chunk} Q[s,d] K[s,e]
//   = Qh·Kh + Qh·Kl + Ql·Kh  (fp32 accumulators; Ql·Kl term ~1e-8, dropped)
// mma m=d, n=e, k=s. Operands stored [s][channel]; fragments built with
// ldmatrix.trans. Rows padded to 72 fp16 (144 B): 8-row trans phases hit
// 8 disjoint 16B segments -> conflict-free.
// 256 threads, 8 warps: warp tile d16 x e32. 8 s-subtiles of 64, dbl-buffered.
// ---------------------------------------------------------------------------
#define GROW   144                 /* bytes per padded row */
#define GMAT   (64 * GROW)         /* 9216 per matrix tile */
#define GSTG   (4 * GMAT)          /* 36864 per stage */
#define GR_SMEM (2 * GSTG)         /* 73728 */

static __device__ __forceinline__ void gram_load(
    uint32_t sb, int buf,
    const __half* __restrict__ Qh, const __half* __restrict__ Ql,
    const __half* __restrict__ Kh, const __half* __restrict__ Kl,
    size_t base, int tid)
{
    const uint32_t st = sb + buf * GSTG;
    #pragma unroll
    for (int i = 0; i < 2; i++) {
        const int slot = i * 256 + tid;          // 0..511
        const int row = slot >> 3;               // 0..63 (s)
        const int seg = slot & 7;                // 16B segment
        const uint32_t d = row * GROW + seg * 16;
        const size_t g = base + (size_t)row * EMBED + seg * 8;
        cp16(st + 0 * GMAT + d, Qh + g);
        cp16(st + 1 * GMAT + d, Ql + g);
        cp16(st + 2 * GMAT + d, Kh + g);
        cp16(st + 3 * GMAT + d, Kl + g);
    }
    CP_COMMIT();
}

__global__ __launch_bounds__(256, 2)
void gram_kernel(const __half* __restrict__ Qh, const __half* __restrict__ Ql,
                 const __half* __restrict__ Kh, const __half* __restrict__ Kl)
{
    extern __shared__ char smem[];
    const uint32_t sb = smem_u32(smem);

    const int bh = blockIdx.x & (BHEADS - 1);
    const int chunk = blockIdx.x >> 7;
    const int b = bh >> 4, h = bh & 15;
    const size_t base0 = ((size_t)b * SEQ + (size_t)chunk * SCHUNK) * EMBED + h * DK;

    const int tid = threadIdx.x;
    const int wid = tid >> 5;
    const int lane = tid & 31;
    const int g = lane >> 2, tg = lane & 3;
    const int grp = lane >> 3, lr8 = lane & 7;

    const int wm = wid & 3;              // d-tile 0..3 (16 each)
    const int wn = wid >> 2;             // e-tile 0..1 (32 each)

    // A (trans): tiles (m=d, k=s): source rows s = kb+lr8, col-bytes = d*2
    const uint32_t aoff = (uint32_t)(((grp >> 1) * 8 + lr8) * GROW
                                     + (wm * 16 + (grp & 1) * 8) * 2);
    // B (trans): tiles (n=e, k=s): source rows s = kb2+lr8, col-bytes = e*2
    const uint32_t boff = (uint32_t)(((grp & 1) * 8 + lr8) * GROW
                                     + (wn * 32 + (grp >> 1) * 8) * 2);

    float acc[4][4];
    #pragma unroll
    for (int nt = 0; nt < 4; nt++)
        #pragma unroll
        for (int r = 0; r < 4; r++) acc[nt][r] = 0.f;

    gram_load(sb, 0, Qh, Ql, Kh, Kl, base0, tid);

    #pragma unroll 1
    for (int st = 0; st < SCHUNK / 64; st++) {
        const int buf = st & 1;
        if (st + 1 < SCHUNK / 64) {
            gram_load(sb, buf ^ 1, Qh, Ql, Kh, Kl,
                      base0 + (size_t)(st + 1) * 64 * EMBED, tid);
            CP_WAIT(1);
        } else {
            CP_WAIT(0);
        }
        __syncthreads();

        const uint32_t sQh = sb + buf * GSTG;
        const uint32_t sQl = sQh + GMAT;
        const uint32_t sKh = sQh + 2 * GMAT;
        const uint32_t sKl = sQh + 3 * GMAT;

        #pragma unroll
        for (int ks = 0; ks < 4; ks++) {
            const uint32_t so = ks * 16 * GROW;  // 16 s-rows down

            uint32_t qh4[4], ql4[4];
            ldsm4t(qh4, sQh + aoff + so);
            ldsm4t(ql4, sQl + aoff + so);
            uint32_t kha[4], khb[4], kla[4], klb[4];
            ldsm4t(kha, sKh + boff + so);        // e in [wn*32, wn*32+16)
            ldsm4t(khb, sKh + boff + 32 + so);   // e in [wn*32+16, wn*32+32)
            ldsm4t(kla, sKl + boff + so);
            ldsm4t(klb, sKl + boff + 32 + so);

            // pass hi*hi
            hmma(acc[0], qh4, kha[0], kha[1]);
            hmma(acc[1], qh4, kha[2], kha[3]);
            hmma(acc[2], qh4, khb[0], khb[1]);
            hmma(acc[3], qh4, khb[2], khb[3]);
            // pass hi*lo
            hmma(acc[0], qh4, kla[0], kla[1]);
            hmma(acc[1], qh4, kla[2], kla[3]);
            hmma(acc[2], qh4, klb[0], klb[1]);
            hmma(acc[3], qh4, klb[2], klb[3]);
            // pass lo*hi
            hmma(acc[0], ql4, kha[0], kha[1]);
            hmma(acc[1], ql4, kha[2], kha[3]);
            hmma(acc[2], ql4, khb[0], khb[1]);
            hmma(acc[3], ql4, khb[2], khb[3]);
        }
        __syncthreads();
    }

    float* gp = g_Gpart + ((size_t)chunk * BHEADS + bh) * DK * DK;
    const int d0 = wm * 16 + g;
    #pragma unroll
    for (int nt = 0; nt < 4; nt++) {
        const int e0 = wn * 32 + nt * 8 + 2 * tg;
        *(float2*)&gp[d0 * DK + e0]       = make_float2(acc[nt][0], acc[nt][1]);
        *(float2*)&gp[(d0 + 8) * DK + e0] = make_float2(acc[nt][2], acc[nt][3]);
    }
}

// ---------------------------------------------------------------------------
// Kernel E: reduce partials + softmax; write fp16 attn [d][e] row-major
// ---------------------------------------------------------------------------
__global__ __launch_bounds__(256)
void softmax_kernel()
{
    const int gwarp = (blockIdx.x * blockDim.x + threadIdx.x) >> 5;
    const int lane = threadIdx.x & 31;
    const int bh = gwarp >> 6;
    const int d = gwarp & 63;

    float g0 = 0.f, g1 = 0.f;
    #pragma unroll
    for (int c = 0; c < NCHUNK; c++) {
        const float* gp = g_Gpart + (((size_t)c * BHEADS + bh) * DK + d) * DK;
        g0 += gp[lane];
        g1 += gp[lane + 32];
    }
    g0 *= 0.125f; g1 *= 0.125f;

    float m = fmaxf(g0, g1);
    #pragma unroll
    for (int o = 16; o > 0; o >>= 1) m = fmaxf(m, __shfl_xor_sync(0xffffffffu, m, o));
    float e0 = expf(g0 - m), e1 = expf(g1 - m);
    float s = e0 + e1;
    #pragma unroll
    for (int o = 16; o > 0; o >>= 1) s += __shfl_xor_sync(0xffffffffu, s, o);
    const float inv = 1.0f / s;

    __half* at = g_Ath + (size_t)bh * DK * DK;
    at[d * DK + lane]      = __float2half_rn(e0 * inv);
    at[d * DK + lane + 32] = __float2half_rn(e1 * inv);
}

// ---------------------------------------------------------------------------
// Kernel F: HMMA output mix.
//   out[m][h*64+d] = sum_e attn[bh][d][e] * V[m][h*64+e]
// ---------------------------------------------------------------------------
#define PADO 72
#define OROW (PADO * 2)     /* 144 bytes */

__global__ __launch_bounds__(256, 2)
void out_hmma_kernel(const __half* __restrict__ Vh, float* __restrict__ OUT)
{
    __shared__ __align__(16) char sm[128 * OROW + 64 * OROW];

    const int m0 = blockIdx.x * 128;
    const int h  = blockIdx.y;
    const int b  = m0 >> 12;
    const int bh = b * NHEADS + h;

    const int tid = threadIdx.x;
    const int wid = tid >> 5;
    const int lane = tid & 31;
    const int g = lane >> 2, tg = lane & 3;
    const int grp = lane >> 3, lr8 = lane & 7;

    // load V tile [128 x 64] fp16 -> smem rows of 144 B
    #pragma unroll
    for (int i = 0; i < 4; i++) {
        const int slot = i * 256 + tid;          // 0..1023
        const int row = slot >> 3, seg = slot & 7;
        *(uint4*)(sm + row * OROW + seg * 16) =
            *(const uint4*)(Vh + (size_t)(m0 + row) * EMBED + h * 64 + seg * 8);
    }
    // load attn [64 x 64] fp16
    const __half* at = g_Ath + (size_t)bh * DK * DK;
    #pragma unroll
    for (int i = 0; i < 2; i++) {
        const int slot = i * 256 + tid;          // 0..511
        const int row = slot >> 3, seg = slot & 7;
        *(uint4*)(sm + 128 * OROW + row * OROW + seg * 16) =
            *(const uint4*)(at + row * 64 + seg * 8);
    }
    __syncthreads();

    const uint32_t sb = smem_u32(sm);
    const uint32_t aoff = sb + (uint32_t)((wid * 16 + (grp & 1) * 8 + lr8) * OROW
                                          + (grp >> 1) * 16);
    const uint32_t boff = sb + 128 * OROW
                        + (uint32_t)(((grp >> 1) * 8 + lr8) * OROW + (grp & 1) * 16);

    float acc[8][4];
    #pragma unroll
    for (int nt = 0; nt < 8; nt++)
        #pragma unroll
        for (int r = 0; r < 4; r++) acc[nt][r] = 0.f;

    #pragma unroll
    for (int ks = 0; ks < 4; ks++) {
        const uint32_t so = ks * 32;             // 16 fp16 along e
        uint32_t a4[4];
        ldsm4(a4, aoff + so);
        #pragma unroll
        for (int pr = 0; pr < 4; pr++) {
            uint32_t b4[4];
            ldsm4(b4, boff + pr * (16 * OROW) + so);
            hmma(acc[2 * pr],     a4, b4[0], b4[1]);
            hmma(acc[2 * pr + 1], a4, b4[2], b4[3]);
        }
    }

    const int row = m0 + wid * 16 + g;
    #pragma unroll
    for (int nt = 0; nt < 8; nt++) {
        const int col = h * 64 + nt * 8 + 2 * tg;
        *(float2*)&OUT[(size_t)row * EMBED + col] =
            make_float2(acc[nt][0], acc[nt][1]);
        *(float2*)&OUT[(size_t)(row + 8) * EMBED + col] =
            make_float2(acc[nt][2], acc[nt][3]);
    }
}

// ---------------------------------------------------------------------------
// Launch
// ---------------------------------------------------------------------------
extern "C" void kernel_launch(void* const* d_in, const int* in_sizes, int n_in,
                              void* d_out, int out_size)
{
    const float* x  = (const float*)d_in[0];
    const float* Wq = (const float*)d_in[1];
    const float* bq = (const float*)d_in[2];
    const float* Wk = (const float*)d_in[3];
    const float* bk = (const float*)d_in[4];
    const float* Wv = (const float*)d_in[5];
    const float* bv = (const float*)d_in[6];
    float* out = (float*)d_out;

    cudaFuncSetAttribute(qk_gemm_kernel,
                         cudaFuncAttributeMaxDynamicSharedMemorySize, G_SMEM);
    cudaFuncSetAttribute(v_gemm_kernel,
                         cudaFuncAttributeMaxDynamicSharedMemorySize, G_SMEM);
    cudaFuncSetAttribute(gram_kernel,
                         cudaFuncAttributeMaxDynamicSharedMemorySize, GR_SMEM);

    __half *xh, *wb, *vh, *qh, *ql, *kh, *kl;
    cudaGetSymbolAddress((void**)&xh, g_xh);
    cudaGetSymbolAddress((void**)&wb, g_w);
    cudaGetSymbolAddress((void**)&vh, g_Vh);
    cudaGetSymbolAddress((void**)&qh, g_Qh);
    cudaGetSymbolAddress((void**)&ql, g_Ql);
    cudaGetSymbolAddress((void**)&kh, g_Kh);
    cudaGetSymbolAddress((void**)&kl, g_Kl);

    __half* w0 = wb;
    __half* w1 = wb + EMBED * EMBED;
    __half* w2 = wb + 2 * EMBED * EMBED;

    // 1) fused conversions (x and all W -> fp16)
    prep_kernel<<<XB + 3 * WB, 256>>>(x, Wq, Wk, Wv, xh, w0, w1, w2);

    // 2) Q and K projections, fp16 hi/lo outputs (exact to ~2^-21)
    qk_gemm_kernel<<<2 * GEMM_BLOCKS, 256, G_SMEM>>>(
        xh, w0, w1, bq, bk, qh, ql, kh, kl);

    // 3) V projection (fp16 out), then HMMA gram (3-pass hi/lo)
    v_gemm_kernel<<<GEMM_BLOCKS, 256, G_SMEM>>>(xh, w2, bv, vh);
    gram_kernel<<<GRAM_BLOCKS, 256, GR_SMEM>>>(qh, ql, kh, kl);

    // 4) softmax (fp16 attn) + HMMA output mix
    softmax_kernel<<<(BHEADS * DK) / 8, 256>>>();
    out_hmma_kernel<<<dim3(MTOK / 128, NHEADS), 256>>>(vh, out);
}